// round 4
// baseline (speedup 1.0000x reference)
#include <cuda_runtime.h>
#include <math.h>
#include <stdint.h>

// 128x128 tile, BK=8, 256 threads, 8x8 micro-tile.
#define BM 128
#define BN 128
#define BK 8
#define PAD 4

// ---------------------------------------------------------------------------
// Kernel 1: scores[b,c,s] = sum_h W[cand[b,c],h] * x[b,s,h]  (masked -> -inf)
// ---------------------------------------------------------------------------
__global__ __launch_bounds__(256) void scores_kernel(
    const float* __restrict__ x,            // [B,S,H]
    const int* __restrict__ masks,          // [B,S] int32
    const int* __restrict__ cand,           // [B,C] int32
    const float* __restrict__ w,            // [L+1,H]
    float* __restrict__ attn,               // [B,C,S]
    int B, int S, int H, int C, int Lmax)
{
    __shared__ float As[BK][BM + PAD];
    __shared__ float Bs[BK][BN + PAD];
    __shared__ const float* qrow[BM];

    const int b  = blockIdx.z;
    const int c0 = blockIdx.y * BM;
    const int s0 = blockIdx.x * BN;
    const int tid = threadIdx.x;

    if (tid < BM) {
        int c  = c0 + tid;
        int cc = c < C ? c : (C - 1);
        int lbl = cand[(size_t)b * C + cc];
        if (lbl < 0) lbl = 0;
        if (lbl > Lmax) lbl = Lmax;
        qrow[tid] = w + (size_t)lbl * H;
    }
    __syncthreads();

    // load mapping: row = tid/2 (0..127), k offset = (tid&1)*4
    const int lr = tid >> 1;
    const int lk = (tid & 1) * 4;
    // micro mapping: ty = c-group (0..15), tx = s-group (0..15)
    const int ty = tid >> 4;
    const int tx = tid & 15;

    const float* xb = x + ((size_t)b * S + s0) * H;

    float acc[8][8];
    #pragma unroll
    for (int i = 0; i < 8; i++)
        #pragma unroll
        for (int j = 0; j < 8; j++) acc[i][j] = 0.f;

    const float* aptr = qrow[lr] + lk;

    for (int k0 = 0; k0 < H; k0 += BK) {
        float4 av = *(const float4*)(aptr + k0);
        As[lk + 0][lr] = av.x; As[lk + 1][lr] = av.y;
        As[lk + 2][lr] = av.z; As[lk + 3][lr] = av.w;
        float4 bv = *(const float4*)(xb + (size_t)lr * H + k0 + lk);
        Bs[lk + 0][lr] = bv.x; Bs[lk + 1][lr] = bv.y;
        Bs[lk + 2][lr] = bv.z; Bs[lk + 3][lr] = bv.w;
        __syncthreads();

        #pragma unroll
        for (int k = 0; k < BK; k++) {
            float4 a0 = *(const float4*)&As[k][ty * 8];
            float4 a1 = *(const float4*)&As[k][ty * 8 + 4];
            float4 b0 = *(const float4*)&Bs[k][tx * 8];
            float4 b1 = *(const float4*)&Bs[k][tx * 8 + 4];
            float ar[8] = {a0.x, a0.y, a0.z, a0.w, a1.x, a1.y, a1.z, a1.w};
            float br[8] = {b0.x, b0.y, b0.z, b0.w, b1.x, b1.y, b1.z, b1.w};
            #pragma unroll
            for (int i = 0; i < 8; i++)
                #pragma unroll
                for (int j = 0; j < 8; j++)
                    acc[i][j] += ar[i] * br[j];
        }
        __syncthreads();
    }

    // mask + store
    const int s = s0 + tx * 8;
    int4 m0 = *(const int4*)(masks + (size_t)b * S + s);
    int4 m1 = *(const int4*)(masks + (size_t)b * S + s + 4);
    #pragma unroll
    for (int i = 0; i < 8; i++) {
        int c = c0 + ty * 8 + i;
        if (c >= C) continue;
        float* dst = attn + ((size_t)b * C + c) * S + s;
        float4 o0, o1;
        o0.x = m0.x ? acc[i][0] : -INFINITY;
        o0.y = m0.y ? acc[i][1] : -INFINITY;
        o0.z = m0.z ? acc[i][2] : -INFINITY;
        o0.w = m0.w ? acc[i][3] : -INFINITY;
        o1.x = m1.x ? acc[i][4] : -INFINITY;
        o1.y = m1.y ? acc[i][5] : -INFINITY;
        o1.z = m1.z ? acc[i][6] : -INFINITY;
        o1.w = m1.w ? acc[i][7] : -INFINITY;
        *(float4*)dst = o0;
        *(float4*)(dst + 4) = o1;
    }
}

// ---------------------------------------------------------------------------
// Kernel 2: in-place softmax over S of attn [B*C, S].
// ---------------------------------------------------------------------------
__global__ __launch_bounds__(256) void softmax_kernel(float* __restrict__ attn, int S)
{
    const size_t row = blockIdx.x;
    float* p = attn + row * (size_t)S;
    const int tid = threadIdx.x;
    const int nvec = S / 4;

    __shared__ float red[8];

    float m = -INFINITY;
    for (int i = tid; i < nvec; i += 256) {
        float4 v = ((const float4*)p)[i];
        m = fmaxf(m, fmaxf(fmaxf(v.x, v.y), fmaxf(v.z, v.w)));
    }
    #pragma unroll
    for (int o = 16; o > 0; o >>= 1) m = fmaxf(m, __shfl_xor_sync(0xffffffffu, m, o));
    if ((tid & 31) == 0) red[tid >> 5] = m;
    __syncthreads();
    if (tid < 32) {
        float t = (tid < 8) ? red[tid] : -INFINITY;
        #pragma unroll
        for (int o = 4; o > 0; o >>= 1) t = fmaxf(t, __shfl_xor_sync(0xffffffffu, t, o));
        if (tid == 0) red[0] = t;
    }
    __syncthreads();
    m = red[0];
    __syncthreads();

    float s = 0.f;
    for (int i = tid; i < nvec; i += 256) {
        float4 v = ((const float4*)p)[i];
        v.x = __expf(v.x - m); v.y = __expf(v.y - m);
        v.z = __expf(v.z - m); v.w = __expf(v.w - m);
        s += (v.x + v.y) + (v.z + v.w);
        ((float4*)p)[i] = v;
    }
    #pragma unroll
    for (int o = 16; o > 0; o >>= 1) s += __shfl_xor_sync(0xffffffffu, s, o);
    if ((tid & 31) == 0) red[tid >> 5] = s;
    __syncthreads();
    if (tid < 32) {
        float t = (tid < 8) ? red[tid] : 0.f;
        #pragma unroll
        for (int o = 4; o > 0; o >>= 1) t += __shfl_xor_sync(0xffffffffu, t, o);
        if (tid == 0) red[0] = t;
    }
    __syncthreads();
    const float inv = 1.0f / red[0];

    for (int i = tid; i < nvec; i += 256) {
        float4 v = ((const float4*)p)[i];
        v.x *= inv; v.y *= inv; v.z *= inv; v.w *= inv;
        ((float4*)p)[i] = v;
    }
}

// ---------------------------------------------------------------------------
// Kernel 3: logits[b,c,h] = sum_s attn[b,c,s] * x[b,s,h]
// ---------------------------------------------------------------------------
__global__ __launch_bounds__(256) void logits_kernel(
    const float* __restrict__ attn,   // [B,C,S]
    const float* __restrict__ x,      // [B,S,H]
    float* __restrict__ out,          // [B,C,H]
    int B, int S, int H, int C)
{
    __shared__ float As[BK][BM + PAD];
    __shared__ float Bs[BK][BN + PAD];

    const int b  = blockIdx.z;
    const int c0 = blockIdx.y * BM;
    const int h0 = blockIdx.x * BN;
    const int tid = threadIdx.x;

    // A-load: row = tid/2 (c), k offset = (tid&1)*4
    const int lr = tid >> 1;
    const int lk = (tid & 1) * 4;
    // B-load: k = tid/32 (0..7), h offset = (tid&31)*4
    const int bk = tid >> 5;
    const int bh = (tid & 31) * 4;

    const int ty = tid >> 4;
    const int tx = tid & 15;

    const int ca = (c0 + lr < C) ? (c0 + lr) : (C - 1);
    const float* arow = attn + ((size_t)b * C + ca) * S + lk;
    const float* xb   = x + (size_t)b * S * H + h0 + bh;

    float acc[8][8];
    #pragma unroll
    for (int i = 0; i < 8; i++)
        #pragma unroll
        for (int j = 0; j < 8; j++) acc[i][j] = 0.f;

    for (int k0 = 0; k0 < S; k0 += BK) {
        float4 av = *(const float4*)(arow + k0);
        As[lk + 0][lr] = av.x; As[lk + 1][lr] = av.y;
        As[lk + 2][lr] = av.z; As[lk + 3][lr] = av.w;
        float4 bv = *(const float4*)(xb + (size_t)(k0 + bk) * H);
        *(float4*)&Bs[bk][bh] = bv;
        __syncthreads();

        #pragma unroll
        for (int k = 0; k < BK; k++) {
            float4 a0 = *(const float4*)&As[k][ty * 8];
            float4 a1 = *(const float4*)&As[k][ty * 8 + 4];
            float4 b0 = *(const float4*)&Bs[k][tx * 8];
            float4 b1 = *(const float4*)&Bs[k][tx * 8 + 4];
            float ar[8] = {a0.x, a0.y, a0.z, a0.w, a1.x, a1.y, a1.z, a1.w};
            float br[8] = {b0.x, b0.y, b0.z, b0.w, b1.x, b1.y, b1.z, b1.w};
            #pragma unroll
            for (int i = 0; i < 8; i++)
                #pragma unroll
                for (int j = 0; j < 8; j++)
                    acc[i][j] += ar[i] * br[j];
        }
        __syncthreads();
    }

    const int h = h0 + tx * 8;
    #pragma unroll
    for (int i = 0; i < 8; i++) {
        int c = c0 + ty * 8 + i;
        if (c >= C) continue;
        float* dst = out + ((size_t)b * C + c) * H + h;
        *(float4*)dst       = make_float4(acc[i][0], acc[i][1], acc[i][2], acc[i][3]);
        *(float4*)(dst + 4) = make_float4(acc[i][4], acc[i][5], acc[i][6], acc[i][7]);
    }
}

// ---------------------------------------------------------------------------
// Launch
// ---------------------------------------------------------------------------
extern "C" void kernel_launch(void* const* d_in, const int* in_sizes, int n_in,
                              void* d_out, int out_size)
{
    const float* x     = (const float*)d_in[0];   // [B,S,H]
    const int*   masks = (const int*)d_in[1];     // [B,S]  int32
    const int*   cand  = (const int*)d_in[2];     // [B,C]  int32
    const float* w     = (const float*)d_in[3];   // [L+1,H]

    const long long n0 = in_sizes[0]; // B*S*H
    const long long n1 = in_sizes[1]; // B*S
    const long long n2 = in_sizes[2]; // B*C
    const long long n3 = in_sizes[3]; // (L+1)*H

    const int H  = (int)(n0 / n1);
    const int HS = (int)((long long)out_size / n2); // H + S
    const int S  = HS - H;
    const int B  = (int)(n1 / S);
    const int C  = (int)(n2 / B);
    const int Lmax = (int)(n3 / H) - 1;

    float* logits = (float*)d_out;               // [B,C,H]
    float* attn   = logits + (size_t)B * C * H;  // [B,C,S]

    dim3 blk(256);

    dim3 g1(S / BN, (C + BM - 1) / BM, B);
    scores_kernel<<<g1, blk>>>(x, masks, cand, w, attn, B, S, H, C, Lmax);

    dim3 g2((unsigned)((size_t)B * C));
    softmax_kernel<<<g2, blk>>>(attn, S);

    dim3 g3(H / BN, (C + BM - 1) / BM, B);
    logits_kernel<<<g3, blk>>>(attn, x, logits, B, S, H, C);
}

// round 6
// speedup vs baseline: 1.4275x; 1.4275x over previous
#include <cuda_runtime.h>
#include <cuda_bf16.h>
#include <math.h>
#include <stdint.h>

#define PITCH 72          // bf16 elems per smem row: 64 + 8 pad (144B = 9*16B, odd)
#define TILE_B (128 * PITCH * 2)   // 18432 bytes per tile
#define SM_QROW 0         // [0:1024)  gathered row pointers (K1)
#define SM_MASK 1024      // [1024:1536) mask ints (K1)
#define SM_TILES 2048     // AHI | ALO | BHI | BLO
#define SMEM_TOTAL (SM_TILES + 4 * TILE_B)

__device__ __forceinline__ uint32_t smem_u32(const void* p) {
    uint32_t a;
    asm("{ .reg .u64 t; cvta.to.shared.u64 t, %1; cvt.u32.u64 %0, t; }" : "=r"(a) : "l"(p));
    return a;
}
__device__ __forceinline__ void ldsm_x4(uint32_t* r, uint32_t a) {
    asm volatile("ldmatrix.sync.aligned.m8n8.x4.shared.b16 {%0,%1,%2,%3}, [%4];"
                 : "=r"(r[0]), "=r"(r[1]), "=r"(r[2]), "=r"(r[3]) : "r"(a));
}
__device__ __forceinline__ void mma16816(float* d, const uint32_t* a, const uint32_t* b) {
    asm volatile(
        "mma.sync.aligned.m16n8k16.row.col.f32.bf16.bf16.f32 "
        "{%0,%1,%2,%3}, {%4,%5,%6,%7}, {%8,%9}, {%0,%1,%2,%3};"
        : "+f"(d[0]), "+f"(d[1]), "+f"(d[2]), "+f"(d[3])
        : "r"(a[0]), "r"(a[1]), "r"(a[2]), "r"(a[3]), "r"(b[0]), "r"(b[1]));
}
// split 2 floats -> packed bf16x2 hi and lo
__device__ __forceinline__ void split2u(float a, float b, uint32_t& h, uint32_t& l) {
    __nv_bfloat162 hh, ll;
    hh.x = __float2bfloat16(a); hh.y = __float2bfloat16(b);
    ll.x = __float2bfloat16(a - __bfloat162float(hh.x));
    ll.y = __float2bfloat16(b - __bfloat162float(hh.y));
    h = *(uint32_t*)&hh; l = *(uint32_t*)&ll;
}

// ===========================================================================
// Kernel 1: scores[b,c,s] = sum_h W[cand[b,c],h] * x[b,s,h]  (masked -> -inf)
// tile 128c x 128s, K=H chunked by 64; bf16 hi/lo 3-pass on HMMA.
// ===========================================================================
__global__ __launch_bounds__(256) void scores_mma_kernel(
    const float* __restrict__ x, const int* __restrict__ masks,
    const int* __restrict__ cand, const float* __restrict__ w,
    float* __restrict__ attn, int B, int S, int H, int C, int Lmax)
{
    extern __shared__ char dsm[];
    const uint32_t sb = smem_u32(dsm);
    const float** qrow = (const float**)(dsm + SM_QROW);
    int* smask = (int*)(dsm + SM_MASK);
    char* AHI = dsm + SM_TILES;
    char* ALO = AHI + TILE_B;
    char* BHI = ALO + TILE_B;
    char* BLO = BHI + TILE_B;
    const uint32_t uAHI = sb + SM_TILES, uALO = uAHI + TILE_B,
                   uBHI = uALO + TILE_B, uBLO = uBHI + TILE_B;

    const int tid = threadIdx.x;
    const int lane = tid & 31;
    const int wid = tid >> 5;
    const int wm = wid & 3;        // warp m group (32 c)
    const int wn = wid >> 2;       // warp n group (64 s)
    const int b  = blockIdx.z;
    const int c0 = blockIdx.y * 128;
    const int s0 = blockIdx.x * 128;

    if (tid < 128) {
        int c = c0 + tid; if (c >= C) c = C - 1;
        int lbl = cand[(size_t)b * C + c];
        lbl = lbl < 0 ? 0 : (lbl > Lmax ? Lmax : lbl);
        qrow[tid] = w + (size_t)lbl * H;
        smask[tid] = masks[(size_t)b * S + s0 + tid];
    }

    // loader mapping: row = tid>>1 (0..127), half = (tid&1)*32 floats
    const int lrow = tid >> 1;
    const int lhalf = (tid & 1) * 32;
    const float* brow = x + ((size_t)b * S + s0 + lrow) * H + lhalf;
    const uint32_t aoff = (uint32_t)(lrow * PITCH + lhalf) * 2;

    // ldmatrix lane addressing
    const int a_r = lane & 15;             // row within 16
    const int a_k = (lane >> 4) * 8;       // k half
    const int b_n = (lane & 7) | (((lane >> 4) & 1) << 3);
    const int b_k = ((lane >> 3) & 1) * 8;

    float acc[2][8][4];
    #pragma unroll
    for (int i = 0; i < 2; i++)
        #pragma unroll
        for (int j = 0; j < 8; j++)
            #pragma unroll
            for (int q = 0; q < 4; q++) acc[i][j][q] = 0.f;

    __syncthreads();
    const float* arow = qrow[lrow] + lhalf;

    const int nchunks = H >> 6;
    for (int ch = 0; ch < nchunks; ch++) {
        const int kc = ch << 6;
        // ---- load + split A and B into smem ----
        #pragma unroll
        for (int f = 0; f < 8; f++) {
            float4 v = *(const float4*)(arow + kc + 4 * f);
            uint32_t h0, l0, h1, l1;
            split2u(v.x, v.y, h0, l0);
            split2u(v.z, v.w, h1, l1);
            *(uint2*)(AHI + aoff + 8 * f) = make_uint2(h0, h1);
            *(uint2*)(ALO + aoff + 8 * f) = make_uint2(l0, l1);
        }
        #pragma unroll
        for (int f = 0; f < 8; f++) {
            float4 v = *(const float4*)(brow + kc + 4 * f);
            uint32_t h0, l0, h1, l1;
            split2u(v.x, v.y, h0, l0);
            split2u(v.z, v.w, h1, l1);
            *(uint2*)(BHI + aoff + 8 * f) = make_uint2(h0, h1);
            *(uint2*)(BLO + aoff + 8 * f) = make_uint2(l0, l1);
        }
        __syncthreads();

        // ---- compute: 4 x k16 ----
        #pragma unroll
        for (int kk = 0; kk < 64; kk += 16) {
            uint32_t aH[2][4], aL[2][4];
            #pragma unroll
            for (int mt = 0; mt < 2; mt++) {
                uint32_t off = (uint32_t)((wm * 32 + mt * 16 + a_r) * PITCH + kk + a_k) * 2;
                ldsm_x4(aH[mt], uAHI + off);
                ldsm_x4(aL[mt], uALO + off);
            }
            uint32_t bH[4][4], bL[4][4];
            #pragma unroll
            for (int t = 0; t < 4; t++) {
                uint32_t off = (uint32_t)((wn * 64 + t * 16 + b_n) * PITCH + kk + b_k) * 2;
                ldsm_x4(bH[t], uBHI + off);
                ldsm_x4(bL[t], uBLO + off);
            }
            #pragma unroll
            for (int mt = 0; mt < 2; mt++)
                #pragma unroll
                for (int t = 0; t < 4; t++)
                    #pragma unroll
                    for (int hf = 0; hf < 2; hf++) {
                        float* d = acc[mt][2 * t + hf];
                        mma16816(d, aH[mt], &bH[t][hf * 2]);
                        mma16816(d, aH[mt], &bL[t][hf * 2]);
                        mma16816(d, aL[mt], &bH[t][hf * 2]);
                    }
        }
        __syncthreads();
    }

    // ---- epilogue: mask + store ----
    #pragma unroll
    for (int mt = 0; mt < 2; mt++) {
        const int r0 = wm * 32 + mt * 16 + (lane >> 2);
        #pragma unroll
        for (int nt = 0; nt < 8; nt++) {
            const int sl = wn * 64 + nt * 8 + (lane & 3) * 2;
            const float ninf = -INFINITY;
            float2 o0, o1;
            o0.x = smask[sl]     ? acc[mt][nt][0] : ninf;
            o0.y = smask[sl + 1] ? acc[mt][nt][1] : ninf;
            o1.x = smask[sl]     ? acc[mt][nt][2] : ninf;
            o1.y = smask[sl + 1] ? acc[mt][nt][3] : ninf;
            int c = c0 + r0;
            if (c < C)
                *(float2*)(attn + ((size_t)b * C + c) * S + s0 + sl) = o0;
            if (c + 8 < C)
                *(float2*)(attn + ((size_t)b * C + c + 8) * S + s0 + sl) = o1;
        }
    }
}

// ===========================================================================
// Kernel 2: in-place softmax over S of attn [B*C, S]
// ===========================================================================
__global__ __launch_bounds__(256) void softmax_kernel(float* __restrict__ attn, int S)
{
    const size_t row = blockIdx.x;
    float* p = attn + row * (size_t)S;
    const int tid = threadIdx.x;
    const int nvec = S / 4;
    __shared__ float red[8];

    float m = -INFINITY;
    for (int i = tid; i < nvec; i += 256) {
        float4 v = ((const float4*)p)[i];
        m = fmaxf(m, fmaxf(fmaxf(v.x, v.y), fmaxf(v.z, v.w)));
    }
    #pragma unroll
    for (int o = 16; o > 0; o >>= 1) m = fmaxf(m, __shfl_xor_sync(0xffffffffu, m, o));
    if ((tid & 31) == 0) red[tid >> 5] = m;
    __syncthreads();
    if (tid < 32) {
        float t = (tid < 8) ? red[tid] : -INFINITY;
        #pragma unroll
        for (int o = 4; o > 0; o >>= 1) t = fmaxf(t, __shfl_xor_sync(0xffffffffu, t, o));
        if (tid == 0) red[0] = t;
    }
    __syncthreads();
    m = red[0];
    __syncthreads();

    float s = 0.f;
    for (int i = tid; i < nvec; i += 256) {
        float4 v = ((const float4*)p)[i];
        v.x = __expf(v.x - m); v.y = __expf(v.y - m);
        v.z = __expf(v.z - m); v.w = __expf(v.w - m);
        s += (v.x + v.y) + (v.z + v.w);
        ((float4*)p)[i] = v;
    }
    #pragma unroll
    for (int o = 16; o > 0; o >>= 1) s += __shfl_xor_sync(0xffffffffu, s, o);
    if ((tid & 31) == 0) red[tid >> 5] = s;
    __syncthreads();
    if (tid < 32) {
        float t = (tid < 8) ? red[tid] : 0.f;
        #pragma unroll
        for (int o = 4; o > 0; o >>= 1) t += __shfl_xor_sync(0xffffffffu, t, o);
        if (tid == 0) red[0] = t;
    }
    __syncthreads();
    const float inv = 1.0f / red[0];

    for (int i = tid; i < nvec; i += 256) {
        float4 v = ((const float4*)p)[i];
        v.x *= inv; v.y *= inv; v.z *= inv; v.w *= inv;
        ((float4*)p)[i] = v;
    }
}

// ===========================================================================
// Kernel 3: logits[b,c,h] = sum_s attn[b,c,s] * x[b,s,h]
// tile 128c x 128h, K=S chunked by 64; B = x^T via smem transpose.
// ===========================================================================
__global__ __launch_bounds__(256) void logits_mma_kernel(
    const float* __restrict__ attn, const float* __restrict__ x,
    float* __restrict__ out, int B, int S, int H, int C)
{
    extern __shared__ char dsm[];
    const uint32_t sb = smem_u32(dsm);
    char* AHI = dsm + SM_TILES;
    char* ALO = AHI + TILE_B;
    __nv_bfloat16* BHI = (__nv_bfloat16*)(ALO + TILE_B);
    __nv_bfloat16* BLO = BHI + 128 * PITCH;
    const uint32_t uAHI = sb + SM_TILES, uALO = uAHI + TILE_B,
                   uBHI = uALO + TILE_B, uBLO = uBHI + TILE_B;

    const int tid = threadIdx.x;
    const int lane = tid & 31;
    const int wid = tid >> 5;
    const int wm = wid & 3;
    const int wn = wid >> 2;
    const int b  = blockIdx.z;
    const int c0 = blockIdx.y * 128;
    const int h0 = blockIdx.x * 128;

    // A loader: row = tid>>1, half = (tid&1)*32
    const int lrow = tid >> 1;
    const int lhalf = (tid & 1) * 32;
    const int ca = (c0 + lrow < C) ? (c0 + lrow) : (C - 1);
    const float* arow = attn + ((size_t)b * C + ca) * S + lhalf;
    const uint32_t aoff = (uint32_t)(lrow * PITCH + lhalf) * 2;

    // B loader (transpose): s_local = tid>>2 (0..63), hg = (tid&3)*32
    const int bs = tid >> 2;
    const int hg = (tid & 3) * 32;
    const float* bsrc = x + ((size_t)b * S + bs) * H + h0 + hg;

    const int a_r = lane & 15;
    const int a_k = (lane >> 4) * 8;
    const int b_n = (lane & 7) | (((lane >> 4) & 1) << 3);
    const int b_k = ((lane >> 3) & 1) * 8;

    float acc[2][8][4];
    #pragma unroll
    for (int i = 0; i < 2; i++)
        #pragma unroll
        for (int j = 0; j < 8; j++)
            #pragma unroll
            for (int q = 0; q < 4; q++) acc[i][j][q] = 0.f;

    const int nchunks = S >> 6;
    for (int ch = 0; ch < nchunks; ch++) {
        const int kc = ch << 6;
        // ---- A: attention rows, k-major ----
        #pragma unroll
        for (int f = 0; f < 8; f++) {
            float4 v = *(const float4*)(arow + kc + 4 * f);
            uint32_t h0v, l0v, h1v, l1v;
            split2u(v.x, v.y, h0v, l0v);
            split2u(v.z, v.w, h1v, l1v);
            *(uint2*)(AHI + aoff + 8 * f) = make_uint2(h0v, h1v);
            *(uint2*)(ALO + aoff + 8 * f) = make_uint2(l0v, l1v);
        }
        // ---- B: x[kc+bs, h0+hg..] -> smem [h][s] transposed ----
        #pragma unroll
        for (int f = 0; f < 8; f++) {
            float4 v = *(const float4*)(bsrc + (size_t)kc * H + 4 * f);
            float va[4] = {v.x, v.y, v.z, v.w};
            #pragma unroll
            for (int i = 0; i < 4; i++) {
                int hl = hg + 4 * f + i;
                __nv_bfloat16 hh = __float2bfloat16(va[i]);
                __nv_bfloat16 ll = __float2bfloat16(va[i] - __bfloat162float(hh));
                BHI[hl * PITCH + bs] = hh;
                BLO[hl * PITCH + bs] = ll;
            }
        }
        __syncthreads();

        #pragma unroll
        for (int kk = 0; kk < 64; kk += 16) {
            uint32_t aH[2][4], aL[2][4];
            #pragma unroll
            for (int mt = 0; mt < 2; mt++) {
                uint32_t off = (uint32_t)((wm * 32 + mt * 16 + a_r) * PITCH + kk + a_k) * 2;
                ldsm_x4(aH[mt], uAHI + off);
                ldsm_x4(aL[mt], uALO + off);
            }
            uint32_t bH[4][4], bL[4][4];
            #pragma unroll
            for (int t = 0; t < 4; t++) {
                uint32_t off = (uint32_t)((wn * 64 + t * 16 + b_n) * PITCH + kk + b_k) * 2;
                ldsm_x4(bH[t], uBHI + off);
                ldsm_x4(bL[t], uBLO + off);
            }
            #pragma unroll
            for (int mt = 0; mt < 2; mt++)
                #pragma unroll
                for (int t = 0; t < 4; t++)
                    #pragma unroll
                    for (int hf = 0; hf < 2; hf++) {
                        float* d = acc[mt][2 * t + hf];
                        mma16816(d, aH[mt], &bH[t][hf * 2]);
                        mma16816(d, aH[mt], &bL[t][hf * 2]);
                        mma16816(d, aL[mt], &bH[t][hf * 2]);
                    }
        }
        __syncthreads();
    }

    // ---- epilogue ----
    #pragma unroll
    for (int mt = 0; mt < 2; mt++) {
        const int r0 = wm * 32 + mt * 16 + (lane >> 2);
        #pragma unroll
        for (int nt = 0; nt < 8; nt++) {
            const int hl = wn * 64 + nt * 8 + (lane & 3) * 2;
            int c = c0 + r0;
            if (c < C)
                *(float2*)(out + ((size_t)b * C + c) * H + h0 + hl) =
                    make_float2(acc[mt][nt][0], acc[mt][nt][1]);
            if (c + 8 < C)
                *(float2*)(out + ((size_t)b * C + c + 8) * H + h0 + hl) =
                    make_float2(acc[mt][nt][2], acc[mt][nt][3]);
        }
    }
}

// ===========================================================================
// Launch
// ===========================================================================
extern "C" void kernel_launch(void* const* d_in, const int* in_sizes, int n_in,
                              void* d_out, int out_size)
{
    const float* x     = (const float*)d_in[0];   // [B,S,H]
    const int*   masks = (const int*)d_in[1];     // [B,S]  int32
    const int*   cand  = (const int*)d_in[2];     // [B,C]  int32
    const float* w     = (const float*)d_in[3];   // [L+1,H]

    const long long n0 = in_sizes[0]; // B*S*H
    const long long n1 = in_sizes[1]; // B*S
    const long long n2 = in_sizes[2]; // B*C
    const long long n3 = in_sizes[3]; // (L+1)*H

    const int H  = (int)(n0 / n1);
    const int HS = (int)((long long)out_size / n2); // H + S
    const int S  = HS - H;
    const int B  = (int)(n1 / S);
    const int C  = (int)(n2 / B);
    const int Lmax = (int)(n3 / H) - 1;

    float* logits = (float*)d_out;               // [B,C,H]
    float* attn   = logits + (size_t)B * C * H;  // [B,C,S]

    static bool attr_set = false;
    if (!attr_set) {
        cudaFuncSetAttribute(scores_mma_kernel, cudaFuncAttributeMaxDynamicSharedMemorySize, SMEM_TOTAL);
        cudaFuncSetAttribute(logits_mma_kernel, cudaFuncAttributeMaxDynamicSharedMemorySize, SMEM_TOTAL);
        attr_set = true;
    }

    dim3 blk(256);

    dim3 g1(S / 128, (C + 127) / 128, B);
    scores_mma_kernel<<<g1, blk, SMEM_TOTAL>>>(x, masks, cand, w, attn, B, S, H, C, Lmax);

    dim3 g2((unsigned)((size_t)B * C));
    softmax_kernel<<<g2, blk>>>(attn, S);

    dim3 g3(H / 128, (C + 127) / 128, B);
    logits_mma_kernel<<<g3, blk, SMEM_TOTAL>>>(attn, x, logits, B, S, H, C);
}

// round 7
// speedup vs baseline: 1.7525x; 1.2277x over previous
#include <cuda_runtime.h>
#include <cuda_bf16.h>
#include <math.h>
#include <stdint.h>

// Problem shape (validated by 4 passing rounds on this problem id)
#define CB 16
#define CS 1024
#define CH 256
#define CC 2000

__device__ __nv_bfloat16 g_qhi[CB * CC * CH];
__device__ __nv_bfloat16 g_qlo[CB * CC * CH];
__device__ __nv_bfloat16 g_xhi[CB * CS * CH];
__device__ __nv_bfloat16 g_xlo[CB * CS * CH];

#define PITCH 72            // k-major tile row: 64 bf16 + 8 pad (144B, odd 16B multiple)
#define TILE_B (128 * PITCH * 2)       // 18432 B
#define PITCHB_BYTES 272    // [k][n] tile row for logits B: 128 bf16 + 8 pad
#define TILEB_B (64 * PITCHB_BYTES)    // 17408 B

#define SMEM_SC (1024 + 2 * 4 * TILE_B)                 // 148480
#define SMEM_LG (2 * 2 * TILE_B + 2 * 2 * TILEB_B)      // 143360

__device__ __forceinline__ uint32_t smem_u32(const void* p) {
    uint32_t a;
    asm("{ .reg .u64 t; cvta.to.shared.u64 t, %1; cvt.u32.u64 %0, t; }" : "=r"(a) : "l"(p));
    return a;
}
__device__ __forceinline__ void cp16(uint32_t dst, const void* src) {
    asm volatile("cp.async.cg.shared.global [%0], [%1], 16;" :: "r"(dst), "l"(src) : "memory");
}
__device__ __forceinline__ void cp_commit() { asm volatile("cp.async.commit_group;" ::: "memory"); }
__device__ __forceinline__ void cp_wait1()  { asm volatile("cp.async.wait_group 1;" ::: "memory"); }
__device__ __forceinline__ void cp_wait0()  { asm volatile("cp.async.wait_group 0;" ::: "memory"); }

__device__ __forceinline__ void ldsm_x4(uint32_t* r, uint32_t a) {
    asm volatile("ldmatrix.sync.aligned.m8n8.x4.shared.b16 {%0,%1,%2,%3}, [%4];"
                 : "=r"(r[0]), "=r"(r[1]), "=r"(r[2]), "=r"(r[3]) : "r"(a));
}
__device__ __forceinline__ void ldsm_x4_t(uint32_t* r, uint32_t a) {
    asm volatile("ldmatrix.sync.aligned.m8n8.x4.trans.shared.b16 {%0,%1,%2,%3}, [%4];"
                 : "=r"(r[0]), "=r"(r[1]), "=r"(r[2]), "=r"(r[3]) : "r"(a));
}
__device__ __forceinline__ void mma16816(float* d, const uint32_t* a, const uint32_t* b) {
    asm volatile(
        "mma.sync.aligned.m16n8k16.row.col.f32.bf16.bf16.f32 "
        "{%0,%1,%2,%3}, {%4,%5,%6,%7}, {%8,%9}, {%0,%1,%2,%3};"
        : "+f"(d[0]), "+f"(d[1]), "+f"(d[2]), "+f"(d[3])
        : "r"(a[0]), "r"(a[1]), "r"(a[2]), "r"(a[3]), "r"(b[0]), "r"(b[1]));
}
__device__ __forceinline__ void split2u(float a, float b, uint32_t& h, uint32_t& l) {
    __nv_bfloat162 hh, ll;
    hh.x = __float2bfloat16(a); hh.y = __float2bfloat16(b);
    ll.x = __float2bfloat16(a - __bfloat162float(hh.x));
    ll.y = __float2bfloat16(b - __bfloat162float(hh.y));
    h = *(uint32_t*)&hh; l = *(uint32_t*)&ll;
}

// ===========================================================================
// prep kernels: one-time fp32 -> bf16 hi/lo splits
// ===========================================================================
__global__ __launch_bounds__(256) void prep_q_kernel(
    const int* __restrict__ cand, const float* __restrict__ w,
    int H, int Lmax, int total4, int hd4)
{
    int i = blockIdx.x * 256 + threadIdx.x;
    if (i >= total4) return;
    int row  = i / hd4;
    int col4 = i - row * hd4;
    int lbl = cand[row];
    lbl = lbl < 0 ? 0 : (lbl > Lmax ? Lmax : lbl);
    float4 v = *(const float4*)(w + (size_t)lbl * H + col4 * 4);
    uint32_t h0, l0, h1, l1;
    split2u(v.x, v.y, h0, l0);
    split2u(v.z, v.w, h1, l1);
    *(uint2*)(g_qhi + (size_t)i * 4) = make_uint2(h0, h1);
    *(uint2*)(g_qlo + (size_t)i * 4) = make_uint2(l0, l1);
}

__global__ __launch_bounds__(256) void prep_x_kernel(const float* __restrict__ x, int total4)
{
    int i = blockIdx.x * 256 + threadIdx.x;
    if (i >= total4) return;
    float4 v = *(const float4*)(x + (size_t)i * 4);
    uint32_t h0, l0, h1, l1;
    split2u(v.x, v.y, h0, l0);
    split2u(v.z, v.w, h1, l1);
    *(uint2*)(g_xhi + (size_t)i * 4) = make_uint2(h0, h1);
    *(uint2*)(g_xlo + (size_t)i * 4) = make_uint2(l0, l1);
}

// ===========================================================================
// Kernel 1: scores = q . x^T  (masked -> -inf), pure cp.async + HMMA pipeline
// tile 128c x 128s, K chunk 64, double-buffered
// ===========================================================================
__global__ __launch_bounds__(256) void scores_mma_kernel(
    const int* __restrict__ masks, float* __restrict__ attn,
    int B, int S, int H, int C)
{
    extern __shared__ char dsm[];
    const uint32_t sb = smem_u32(dsm);
    int* smask = (int*)dsm;

    const int tid = threadIdx.x;
    const int lane = tid & 31;
    const int wid = tid >> 5;
    const int wm = wid & 3;
    const int wn = wid >> 2;
    const int b  = blockIdx.z;
    const int c0 = blockIdx.y * 128;
    const int s0 = blockIdx.x * 128;

    if (tid < 128) smask[tid] = masks[(size_t)b * S + s0 + tid];

    const int a_r = lane & 15;
    const int a_k = (lane >> 4) * 8;
    const int b_n = (lane & 7) | (((lane >> 4) & 1) << 3);
    const int b_k = ((lane >> 3) & 1) * 8;

    float acc[2][8][4];
    #pragma unroll
    for (int i = 0; i < 2; i++)
        #pragma unroll
        for (int j = 0; j < 8; j++)
            #pragma unroll
            for (int q = 0; q < 4; q++) acc[i][j][q] = 0.f;

    // prefetch chunk ch into buffer buf
    auto prefetch = [&](int ch, int buf) {
        const int kc = ch << 6;
        const uint32_t A0 = sb + 1024 + buf * (4 * TILE_B);
        const uint32_t A1 = A0 + TILE_B;
        const uint32_t B0 = A0 + 2 * TILE_B;
        const uint32_t B1 = A0 + 3 * TILE_B;
        #pragma unroll
        for (int j = 0; j < 4; j++) {
            const int q = (tid << 2) + j;         // 0..1023
            const int row = q >> 3;
            const int c16 = q & 7;
            const uint32_t soff = row * 144 + c16 * 16;
            int crow = c0 + row; if (crow >= C) crow = C - 1;
            const size_t qo = ((size_t)b * C + crow) * H + kc + c16 * 8;
            cp16(A0 + soff, g_qhi + qo);
            cp16(A1 + soff, g_qlo + qo);
            const size_t xo = ((size_t)b * S + s0 + row) * H + kc + c16 * 8;
            cp16(B0 + soff, g_xhi + xo);
            cp16(B1 + soff, g_xlo + xo);
        }
        cp_commit();
    };

    prefetch(0, 0);
    const int nch = H >> 6;
    for (int ch = 0; ch < nch; ch++) {
        if (ch + 1 < nch) { prefetch(ch + 1, (ch + 1) & 1); cp_wait1(); }
        else cp_wait0();
        __syncthreads();

        const uint32_t uA0 = sb + 1024 + (ch & 1) * (4 * TILE_B);
        const uint32_t uA1 = uA0 + TILE_B;
        const uint32_t uB0 = uA0 + 2 * TILE_B;
        const uint32_t uB1 = uA0 + 3 * TILE_B;

        #pragma unroll
        for (int kk = 0; kk < 64; kk += 16) {
            uint32_t aH[2][4], aL[2][4];
            #pragma unroll
            for (int mt = 0; mt < 2; mt++) {
                uint32_t off = (uint32_t)((wm * 32 + mt * 16 + a_r) * PITCH + kk + a_k) * 2;
                ldsm_x4(aH[mt], uA0 + off);
                ldsm_x4(aL[mt], uA1 + off);
            }
            uint32_t bH[4][4], bL[4][4];
            #pragma unroll
            for (int t = 0; t < 4; t++) {
                uint32_t off = (uint32_t)((wn * 64 + t * 16 + b_n) * PITCH + kk + b_k) * 2;
                ldsm_x4(bH[t], uB0 + off);
                ldsm_x4(bL[t], uB1 + off);
            }
            #pragma unroll
            for (int mt = 0; mt < 2; mt++)
                #pragma unroll
                for (int t = 0; t < 4; t++)
                    #pragma unroll
                    for (int hf = 0; hf < 2; hf++) {
                        float* d = acc[mt][2 * t + hf];
                        mma16816(d, aH[mt], &bH[t][hf * 2]);
                        mma16816(d, aH[mt], &bL[t][hf * 2]);
                        mma16816(d, aL[mt], &bH[t][hf * 2]);
                    }
        }
        __syncthreads();
    }

    // epilogue: mask + store
    #pragma unroll
    for (int mt = 0; mt < 2; mt++) {
        const int r0 = wm * 32 + mt * 16 + (lane >> 2);
        #pragma unroll
        for (int nt = 0; nt < 8; nt++) {
            const int sl = wn * 64 + nt * 8 + (lane & 3) * 2;
            const float ninf = -INFINITY;
            float2 o0, o1;
            o0.x = smask[sl]     ? acc[mt][nt][0] : ninf;
            o0.y = smask[sl + 1] ? acc[mt][nt][1] : ninf;
            o1.x = smask[sl]     ? acc[mt][nt][2] : ninf;
            o1.y = smask[sl + 1] ? acc[mt][nt][3] : ninf;
            int c = c0 + r0;
            if (c < C)
                *(float2*)(attn + ((size_t)b * C + c) * S + s0 + sl) = o0;
            if (c + 8 < C)
                *(float2*)(attn + ((size_t)b * C + c + 8) * S + s0 + sl) = o1;
        }
    }
}

// ===========================================================================
// Kernel 2: in-place softmax over S of attn [B*C, S]
// ===========================================================================
__global__ __launch_bounds__(256) void softmax_kernel(float* __restrict__ attn, int S)
{
    const size_t row = blockIdx.x;
    float* p = attn + row * (size_t)S;
    const int tid = threadIdx.x;
    const int nvec = S / 4;
    __shared__ float red[8];

    float m = -INFINITY;
    for (int i = tid; i < nvec; i += 256) {
        float4 v = ((const float4*)p)[i];
        m = fmaxf(m, fmaxf(fmaxf(v.x, v.y), fmaxf(v.z, v.w)));
    }
    #pragma unroll
    for (int o = 16; o > 0; o >>= 1) m = fmaxf(m, __shfl_xor_sync(0xffffffffu, m, o));
    if ((tid & 31) == 0) red[tid >> 5] = m;
    __syncthreads();
    if (tid < 32) {
        float t = (tid < 8) ? red[tid] : -INFINITY;
        #pragma unroll
        for (int o = 4; o > 0; o >>= 1) t = fmaxf(t, __shfl_xor_sync(0xffffffffu, t, o));
        if (tid == 0) red[0] = t;
    }
    __syncthreads();
    m = red[0];
    __syncthreads();

    float s = 0.f;
    for (int i = tid; i < nvec; i += 256) {
        float4 v = ((const float4*)p)[i];
        v.x = __expf(v.x - m); v.y = __expf(v.y - m);
        v.z = __expf(v.z - m); v.w = __expf(v.w - m);
        s += (v.x + v.y) + (v.z + v.w);
        ((float4*)p)[i] = v;
    }
    #pragma unroll
    for (int o = 16; o > 0; o >>= 1) s += __shfl_xor_sync(0xffffffffu, s, o);
    if ((tid & 31) == 0) red[tid >> 5] = s;
    __syncthreads();
    if (tid < 32) {
        float t = (tid < 8) ? red[tid] : 0.f;
        #pragma unroll
        for (int o = 4; o > 0; o >>= 1) t += __shfl_xor_sync(0xffffffffu, t, o);
        if (tid == 0) red[0] = t;
    }
    __syncthreads();
    const float inv = 1.0f / red[0];

    for (int i = tid; i < nvec; i += 256) {
        float4 v = ((const float4*)p)[i];
        v.x *= inv; v.y *= inv; v.z *= inv; v.w *= inv;
        ((float4*)p)[i] = v;
    }
}

// ===========================================================================
// Kernel 3: logits = attn . x   (A converted in-kernel; B cp.async + trans ldsm)
// tile 128c x 128h, K=S chunk 64, double-buffered
// ===========================================================================
__global__ __launch_bounds__(256) void logits_mma_kernel(
    const float* __restrict__ attn, float* __restrict__ out,
    int B, int S, int H, int C)
{
    extern __shared__ char dsm[];
    const uint32_t sb = smem_u32(dsm);

    const int tid = threadIdx.x;
    const int lane = tid & 31;
    const int wid = tid >> 5;
    const int wm = wid & 3;
    const int wn = wid >> 2;
    const int b  = blockIdx.z;
    const int c0 = blockIdx.y * 128;
    const int h0 = blockIdx.x * 128;

    // A converter mapping
    const int lrow = tid >> 1;
    const int lhalf = (tid & 1) * 32;
    const int ca = (c0 + lrow < C) ? (c0 + lrow) : (C - 1);
    const float* arow = attn + ((size_t)b * C + ca) * S + lhalf;
    const uint32_t aoff = (uint32_t)(lrow * PITCH + lhalf) * 2;

    const int a_r = lane & 15;
    const int a_k = (lane >> 4) * 8;

    float acc[2][8][4];
    #pragma unroll
    for (int i = 0; i < 2; i++)
        #pragma unroll
        for (int j = 0; j < 8; j++)
            #pragma unroll
            for (int q = 0; q < 4; q++) acc[i][j][q] = 0.f;

    auto prefetchB = [&](int ch, int buf) {
        const int kc = ch << 6;
        const uint32_t B0 = sb + 4 * TILE_B + buf * (2 * TILEB_B);
        const uint32_t B1 = B0 + TILEB_B;
        #pragma unroll
        for (int j = 0; j < 4; j++) {
            const int q = (tid << 2) + j;       // 0..1023
            const int row = q >> 4;             // 0..63 (k = s)
            const int c16 = q & 15;             // 16 chunks of 16B across 128 h
            const uint32_t soff = row * PITCHB_BYTES + c16 * 16;
            const size_t xo = ((size_t)b * S + kc + row) * H + h0 + c16 * 8;
            cp16(B0 + soff, g_xhi + xo);
            cp16(B1 + soff, g_xlo + xo);
        }
        cp_commit();
    };
    auto convertA = [&](int ch, int buf) {
        const int kc = ch << 6;
        char* A0 = dsm + buf * (2 * TILE_B);
        char* A1 = A0 + TILE_B;
        #pragma unroll
        for (int f = 0; f < 8; f++) {
            float4 v = *(const float4*)(arow + kc + 4 * f);
            uint32_t h0v, l0v, h1v, l1v;
            split2u(v.x, v.y, h0v, l0v);
            split2u(v.z, v.w, h1v, l1v);
            *(uint2*)(A0 + aoff + 8 * f) = make_uint2(h0v, h1v);
            *(uint2*)(A1 + aoff + 8 * f) = make_uint2(l0v, l1v);
        }
    };

    prefetchB(0, 0);
    convertA(0, 0);
    const int nch = S >> 6;
    for (int ch = 0; ch < nch; ch++) {
        if (ch + 1 < nch) {
            prefetchB(ch + 1, (ch + 1) & 1);
            convertA(ch + 1, (ch + 1) & 1);
            cp_wait1();
        } else cp_wait0();
        __syncthreads();

        const int buf = ch & 1;
        const uint32_t uA0 = sb + buf * (2 * TILE_B);
        const uint32_t uA1 = uA0 + TILE_B;
        const uint32_t uB0 = sb + 4 * TILE_B + buf * (2 * TILEB_B);
        const uint32_t uB1 = uB0 + TILEB_B;

        #pragma unroll
        for (int kk = 0; kk < 64; kk += 16) {
            uint32_t aH[2][4], aL[2][4];
            #pragma unroll
            for (int mt = 0; mt < 2; mt++) {
                uint32_t off = (uint32_t)((wm * 32 + mt * 16 + a_r) * PITCH + kk + a_k) * 2;
                ldsm_x4(aH[mt], uA0 + off);
                ldsm_x4(aL[mt], uA1 + off);
            }
            uint32_t bH[4][4], bL[4][4];
            #pragma unroll
            for (int t = 0; t < 4; t++) {
                uint32_t off = (uint32_t)(kk + (lane & 15)) * PITCHB_BYTES
                             + (uint32_t)(wn * 64 + t * 16 + ((lane >> 4) << 3)) * 2;
                ldsm_x4_t(bH[t], uB0 + off);
                ldsm_x4_t(bL[t], uB1 + off);
            }
            #pragma unroll
            for (int mt = 0; mt < 2; mt++)
                #pragma unroll
                for (int t = 0; t < 4; t++)
                    #pragma unroll
                    for (int hf = 0; hf < 2; hf++) {
                        float* d = acc[mt][2 * t + hf];
                        mma16816(d, aH[mt], &bH[t][hf * 2]);
                        mma16816(d, aH[mt], &bL[t][hf * 2]);
                        mma16816(d, aL[mt], &bH[t][hf * 2]);
                    }
        }
        __syncthreads();
    }

    #pragma unroll
    for (int mt = 0; mt < 2; mt++) {
        const int r0 = wm * 32 + mt * 16 + (lane >> 2);
        #pragma unroll
        for (int nt = 0; nt < 8; nt++) {
            const int hl = wn * 64 + nt * 8 + (lane & 3) * 2;
            int c = c0 + r0;
            if (c < C)
                *(float2*)(out + ((size_t)b * C + c) * H + h0 + hl) =
                    make_float2(acc[mt][nt][0], acc[mt][nt][1]);
            if (c + 8 < C)
                *(float2*)(out + ((size_t)b * C + c + 8) * H + h0 + hl) =
                    make_float2(acc[mt][nt][2], acc[mt][nt][3]);
        }
    }
}

// ===========================================================================
// Launch
// ===========================================================================
extern "C" void kernel_launch(void* const* d_in, const int* in_sizes, int n_in,
                              void* d_out, int out_size)
{
    const float* x     = (const float*)d_in[0];   // [B,S,H]
    const int*   masks = (const int*)d_in[1];     // [B,S]
    const int*   cand  = (const int*)d_in[2];     // [B,C]
    const float* w     = (const float*)d_in[3];   // [L+1,H]

    const long long n0 = in_sizes[0];
    const long long n1 = in_sizes[1];
    const long long n2 = in_sizes[2];
    const long long n3 = in_sizes[3];

    const int H  = (int)(n0 / n1);
    const int HS = (int)((long long)out_size / n2);
    const int S  = HS - H;
    const int B  = (int)(n1 / S);
    const int C  = (int)(n2 / B);
    const int Lmax = (int)(n3 / H) - 1;

    float* logits = (float*)d_out;
    float* attn   = logits + (size_t)B * C * H;

    static bool attr_set = false;
    if (!attr_set) {
        cudaFuncSetAttribute(scores_mma_kernel, cudaFuncAttributeMaxDynamicSharedMemorySize, SMEM_SC);
        cudaFuncSetAttribute(logits_mma_kernel, cudaFuncAttributeMaxDynamicSharedMemorySize, SMEM_LG);
        attr_set = true;
    }

    dim3 blk(256);

    // prep: fp32 -> bf16 hi/lo
    const int qtotal4 = B * C * H / 4;
    const int xtotal4 = B * S * H / 4;
    prep_q_kernel<<<(qtotal4 + 255) / 256, blk>>>(cand, w, H, Lmax, qtotal4, H / 4);
    prep_x_kernel<<<(xtotal4 + 255) / 256, blk>>>(x, xtotal4);

    dim3 g1(S / 128, (C + 127) / 128, B);
    scores_mma_kernel<<<g1, blk, SMEM_SC>>>(masks, attn, B, S, H, C);

    dim3 g2((unsigned)((size_t)B * C));
    softmax_kernel<<<g2, blk>>>(attn, S);

    dim3 g3(H / 128, (C + 127) / 128, B);
    logits_mma_kernel<<<g3, blk, SMEM_LG>>>(attn, logits, B, S, H, C);
}

// round 8
// speedup vs baseline: 1.9311x; 1.1019x over previous
#include <cuda_runtime.h>
#include <cuda_bf16.h>
#include <math.h>
#include <stdint.h>

// Problem shape (validated across passing rounds)
#define CB 16
#define CS 1024
#define CH 256
#define CC 2000

__device__ __nv_bfloat16 g_qhi[CB * CC * CH];
__device__ __nv_bfloat16 g_qlo[CB * CC * CH];
__device__ __nv_bfloat16 g_xhi[CB * CS * CH];
__device__ __nv_bfloat16 g_xlo[CB * CS * CH];
__device__ __nv_bfloat16 g_ahi[CB * CC * CS];
__device__ __nv_bfloat16 g_alo[CB * CC * CS];

#define PITCH 72            // k-major tile row: 64 bf16 + 8 pad (144B)
#define TILE_B (128 * PITCH * 2)       // 18432 B
#define PITCHB_BYTES 272    // [k][n] tile row: 128 bf16 + 8 pad
#define TILEB_B (64 * PITCHB_BYTES)    // 17408 B

#define SMEM_SC (1024 + 2 * 4 * TILE_B)                 // 148480
#define SMEM_LG (2 * 2 * TILE_B + 2 * 2 * TILEB_B)      // 143360

__device__ __forceinline__ uint32_t smem_u32(const void* p) {
    uint32_t a;
    asm("{ .reg .u64 t; cvta.to.shared.u64 t, %1; cvt.u32.u64 %0, t; }" : "=r"(a) : "l"(p));
    return a;
}
__device__ __forceinline__ void cp16(uint32_t dst, const void* src) {
    asm volatile("cp.async.cg.shared.global [%0], [%1], 16;" :: "r"(dst), "l"(src) : "memory");
}
__device__ __forceinline__ void cp_commit() { asm volatile("cp.async.commit_group;" ::: "memory"); }
__device__ __forceinline__ void cp_wait1()  { asm volatile("cp.async.wait_group 1;" ::: "memory"); }
__device__ __forceinline__ void cp_wait0()  { asm volatile("cp.async.wait_group 0;" ::: "memory"); }

__device__ __forceinline__ void ldsm_x4(uint32_t* r, uint32_t a) {
    asm volatile("ldmatrix.sync.aligned.m8n8.x4.shared.b16 {%0,%1,%2,%3}, [%4];"
                 : "=r"(r[0]), "=r"(r[1]), "=r"(r[2]), "=r"(r[3]) : "r"(a));
}
__device__ __forceinline__ void ldsm_x4_t(uint32_t* r, uint32_t a) {
    asm volatile("ldmatrix.sync.aligned.m8n8.x4.trans.shared.b16 {%0,%1,%2,%3}, [%4];"
                 : "=r"(r[0]), "=r"(r[1]), "=r"(r[2]), "=r"(r[3]) : "r"(a));
}
__device__ __forceinline__ void mma16816(float* d, const uint32_t* a, const uint32_t* b) {
    asm volatile(
        "mma.sync.aligned.m16n8k16.row.col.f32.bf16.bf16.f32 "
        "{%0,%1,%2,%3}, {%4,%5,%6,%7}, {%8,%9}, {%0,%1,%2,%3};"
        : "+f"(d[0]), "+f"(d[1]), "+f"(d[2]), "+f"(d[3])
        : "r"(a[0]), "r"(a[1]), "r"(a[2]), "r"(a[3]), "r"(b[0]), "r"(b[1]));
}
__device__ __forceinline__ void split2u(float a, float b, uint32_t& h, uint32_t& l) {
    __nv_bfloat162 hh, ll;
    hh.x = __float2bfloat16(a); hh.y = __float2bfloat16(b);
    ll.x = __float2bfloat16(a - __bfloat162float(hh.x));
    ll.y = __float2bfloat16(b - __bfloat162float(hh.y));
    h = *(uint32_t*)&hh; l = *(uint32_t*)&ll;
}

// ===========================================================================
// prep kernels: one-time fp32 -> bf16 hi/lo splits
// ===========================================================================
__global__ __launch_bounds__(256) void prep_q_kernel(
    const int* __restrict__ cand, const float* __restrict__ w,
    int H, int Lmax, int total4, int hd4)
{
    int i = blockIdx.x * 256 + threadIdx.x;
    if (i >= total4) return;
    int row  = i / hd4;
    int col4 = i - row * hd4;
    int lbl = cand[row];
    lbl = lbl < 0 ? 0 : (lbl > Lmax ? Lmax : lbl);
    float4 v = *(const float4*)(w + (size_t)lbl * H + col4 * 4);
    uint32_t h0, l0, h1, l1;
    split2u(v.x, v.y, h0, l0);
    split2u(v.z, v.w, h1, l1);
    *(uint2*)(g_qhi + (size_t)i * 4) = make_uint2(h0, h1);
    *(uint2*)(g_qlo + (size_t)i * 4) = make_uint2(l0, l1);
}

__global__ __launch_bounds__(256) void prep_x_kernel(const float* __restrict__ x, int total4)
{
    int i = blockIdx.x * 256 + threadIdx.x;
    if (i >= total4) return;
    float4 v = *(const float4*)(x + (size_t)i * 4);
    uint32_t h0, l0, h1, l1;
    split2u(v.x, v.y, h0, l0);
    split2u(v.z, v.w, h1, l1);
    *(uint2*)(g_xhi + (size_t)i * 4) = make_uint2(h0, h1);
    *(uint2*)(g_xlo + (size_t)i * 4) = make_uint2(l0, l1);
}

// ===========================================================================
// Kernel 1: scores = q . x^T  (masked -> -inf), pure cp.async + HMMA pipeline
// ===========================================================================
__global__ __launch_bounds__(256) void scores_mma_kernel(
    const int* __restrict__ masks, float* __restrict__ attn,
    int B, int S, int H, int C)
{
    extern __shared__ char dsm[];
    const uint32_t sb = smem_u32(dsm);
    int* smask = (int*)dsm;

    const int tid = threadIdx.x;
    const int lane = tid & 31;
    const int wid = tid >> 5;
    const int wm = wid & 3;
    const int wn = wid >> 2;
    const int b  = blockIdx.z;
    const int c0 = blockIdx.y * 128;
    const int s0 = blockIdx.x * 128;

    if (tid < 128) smask[tid] = masks[(size_t)b * S + s0 + tid];

    const int a_r = lane & 15;
    const int a_k = (lane >> 4) * 8;
    const int b_n = (lane & 7) | (((lane >> 4) & 1) << 3);
    const int b_k = ((lane >> 3) & 1) * 8;

    float acc[2][8][4];
    #pragma unroll
    for (int i = 0; i < 2; i++)
        #pragma unroll
        for (int j = 0; j < 8; j++)
            #pragma unroll
            for (int q = 0; q < 4; q++) acc[i][j][q] = 0.f;

    auto prefetch = [&](int ch, int buf) {
        const int kc = ch << 6;
        const uint32_t A0 = sb + 1024 + buf * (4 * TILE_B);
        const uint32_t A1 = A0 + TILE_B;
        const uint32_t B0 = A0 + 2 * TILE_B;
        const uint32_t B1 = A0 + 3 * TILE_B;
        #pragma unroll
        for (int j = 0; j < 4; j++) {
            const int q = (tid << 2) + j;
            const int row = q >> 3;
            const int c16 = q & 7;
            const uint32_t soff = row * 144 + c16 * 16;
            int crow = c0 + row; if (crow >= C) crow = C - 1;
            const size_t qo = ((size_t)b * C + crow) * H + kc + c16 * 8;
            cp16(A0 + soff, g_qhi + qo);
            cp16(A1 + soff, g_qlo + qo);
            const size_t xo = ((size_t)b * S + s0 + row) * H + kc + c16 * 8;
            cp16(B0 + soff, g_xhi + xo);
            cp16(B1 + soff, g_xlo + xo);
        }
        cp_commit();
    };

    prefetch(0, 0);
    const int nch = H >> 6;
    for (int ch = 0; ch < nch; ch++) {
        if (ch + 1 < nch) { prefetch(ch + 1, (ch + 1) & 1); cp_wait1(); }
        else cp_wait0();
        __syncthreads();

        const uint32_t uA0 = sb + 1024 + (ch & 1) * (4 * TILE_B);
        const uint32_t uA1 = uA0 + TILE_B;
        const uint32_t uB0 = uA0 + 2 * TILE_B;
        const uint32_t uB1 = uA0 + 3 * TILE_B;

        #pragma unroll
        for (int kk = 0; kk < 64; kk += 16) {
            uint32_t aH[2][4], aL[2][4];
            #pragma unroll
            for (int mt = 0; mt < 2; mt++) {
                uint32_t off = (uint32_t)((wm * 32 + mt * 16 + a_r) * PITCH + kk + a_k) * 2;
                ldsm_x4(aH[mt], uA0 + off);
                ldsm_x4(aL[mt], uA1 + off);
            }
            uint32_t bH[4][4], bL[4][4];
            #pragma unroll
            for (int t = 0; t < 4; t++) {
                uint32_t off = (uint32_t)((wn * 64 + t * 16 + b_n) * PITCH + kk + b_k) * 2;
                ldsm_x4(bH[t], uB0 + off);
                ldsm_x4(bL[t], uB1 + off);
            }
            #pragma unroll
            for (int mt = 0; mt < 2; mt++)
                #pragma unroll
                for (int t = 0; t < 4; t++)
                    #pragma unroll
                    for (int hf = 0; hf < 2; hf++) {
                        float* d = acc[mt][2 * t + hf];
                        mma16816(d, aH[mt], &bH[t][hf * 2]);
                        mma16816(d, aH[mt], &bL[t][hf * 2]);
                        mma16816(d, aL[mt], &bH[t][hf * 2]);
                    }
        }
        __syncthreads();
    }

    #pragma unroll
    for (int mt = 0; mt < 2; mt++) {
        const int r0 = wm * 32 + mt * 16 + (lane >> 2);
        #pragma unroll
        for (int nt = 0; nt < 8; nt++) {
            const int sl = wn * 64 + nt * 8 + (lane & 3) * 2;
            const float ninf = -INFINITY;
            float2 o0, o1;
            o0.x = smask[sl]     ? acc[mt][nt][0] : ninf;
            o0.y = smask[sl + 1] ? acc[mt][nt][1] : ninf;
            o1.x = smask[sl]     ? acc[mt][nt][2] : ninf;
            o1.y = smask[sl + 1] ? acc[mt][nt][3] : ninf;
            int c = c0 + r0;
            if (c < C)
                *(float2*)(attn + ((size_t)b * C + c) * S + s0 + sl) = o0;
            if (c + 8 < C)
                *(float2*)(attn + ((size_t)b * C + c + 8) * S + s0 + sl) = o1;
        }
    }
}

// ===========================================================================
// Kernel 2: fused softmax — warp per row, single read, write fp32 + bf16 hi/lo
// requires S = 128 * 8 = 1024 layout (nf = S/128)
// ===========================================================================
__global__ __launch_bounds__(256) void softmax_fused_kernel(
    float* __restrict__ attn, int S)
{
    const int lane = threadIdx.x & 31;
    const int wrp  = threadIdx.x >> 5;
    const size_t row = (size_t)blockIdx.x * 8 + wrp;
    float* p = attn + row * (size_t)S;
    const int nf = S >> 7;               // float4's per lane (8 for S=1024)

    float4 v[8];
    float m = -INFINITY;
    #pragma unroll
    for (int f = 0; f < 8; f++) {
        if (f < nf) {
            v[f] = ((const float4*)p)[lane + (f << 5)];
            m = fmaxf(m, fmaxf(fmaxf(v[f].x, v[f].y), fmaxf(v[f].z, v[f].w)));
        }
    }
    #pragma unroll
    for (int o = 16; o > 0; o >>= 1) m = fmaxf(m, __shfl_xor_sync(0xffffffffu, m, o));

    float s = 0.f;
    #pragma unroll
    for (int f = 0; f < 8; f++) {
        if (f < nf) {
            v[f].x = __expf(v[f].x - m); v[f].y = __expf(v[f].y - m);
            v[f].z = __expf(v[f].z - m); v[f].w = __expf(v[f].w - m);
            s += (v[f].x + v[f].y) + (v[f].z + v[f].w);
        }
    }
    #pragma unroll
    for (int o = 16; o > 0; o >>= 1) s += __shfl_xor_sync(0xffffffffu, s, o);
    const float inv = 1.0f / s;

    __nv_bfloat16* ph = g_ahi + row * (size_t)S;
    __nv_bfloat16* pl = g_alo + row * (size_t)S;
    #pragma unroll
    for (int f = 0; f < 8; f++) {
        if (f < nf) {
            float4 o;
            o.x = v[f].x * inv; o.y = v[f].y * inv;
            o.z = v[f].z * inv; o.w = v[f].w * inv;
            const int idx = lane + (f << 5);
            ((float4*)p)[idx] = o;
            uint32_t h0, l0, h1, l1;
            split2u(o.x, o.y, h0, l0);
            split2u(o.z, o.w, h1, l1);
            ((uint2*)ph)[idx] = make_uint2(h0, h1);
            ((uint2*)pl)[idx] = make_uint2(l0, l1);
        }
    }
}

// ===========================================================================
// Kernel 3: logits = attn . x — pure cp.async both operands + HMMA pipeline
// ===========================================================================
__global__ __launch_bounds__(256) void logits_mma_kernel(
    float* __restrict__ out, int B, int S, int H, int C)
{
    extern __shared__ char dsm[];
    const uint32_t sb = smem_u32(dsm);

    const int tid = threadIdx.x;
    const int lane = tid & 31;
    const int wid = tid >> 5;
    const int wm = wid & 3;
    const int wn = wid >> 2;
    const int b  = blockIdx.z;
    const int c0 = blockIdx.y * 128;
    const int h0 = blockIdx.x * 128;

    const int a_r = lane & 15;
    const int a_k = (lane >> 4) * 8;

    float acc[2][8][4];
    #pragma unroll
    for (int i = 0; i < 2; i++)
        #pragma unroll
        for (int j = 0; j < 8; j++)
            #pragma unroll
            for (int q = 0; q < 4; q++) acc[i][j][q] = 0.f;

    auto prefetch = [&](int ch, int buf) {
        const int kc = ch << 6;
        const uint32_t A0 = sb + buf * (2 * TILE_B);
        const uint32_t A1 = A0 + TILE_B;
        const uint32_t B0 = sb + 4 * TILE_B + buf * (2 * TILEB_B);
        const uint32_t B1 = B0 + TILEB_B;
        #pragma unroll
        for (int j = 0; j < 4; j++) {
            const int q = (tid << 2) + j;
            {   // A: attention hi/lo, [c][s] k-major
                const int row = q >> 3;
                const int c16 = q & 7;
                const uint32_t soff = row * 144 + c16 * 16;
                int crow = c0 + row; if (crow >= C) crow = C - 1;
                const size_t ao = ((size_t)b * C + crow) * S + kc + c16 * 8;
                cp16(A0 + soff, g_ahi + ao);
                cp16(A1 + soff, g_alo + ao);
            }
            {   // B: x hi/lo, [s][h] natural (trans ldsm later)
                const int row = q >> 4;
                const int c16 = q & 15;
                const uint32_t soff = row * PITCHB_BYTES + c16 * 16;
                const size_t xo = ((size_t)b * S + kc + row) * H + h0 + c16 * 8;
                cp16(B0 + soff, g_xhi + xo);
                cp16(B1 + soff, g_xlo + xo);
            }
        }
        cp_commit();
    };

    prefetch(0, 0);
    const int nch = S >> 6;
    for (int ch = 0; ch < nch; ch++) {
        if (ch + 1 < nch) { prefetch(ch + 1, (ch + 1) & 1); cp_wait1(); }
        else cp_wait0();
        __syncthreads();

        const int buf = ch & 1;
        const uint32_t uA0 = sb + buf * (2 * TILE_B);
        const uint32_t uA1 = uA0 + TILE_B;
        const uint32_t uB0 = sb + 4 * TILE_B + buf * (2 * TILEB_B);
        const uint32_t uB1 = uB0 + TILEB_B;

        #pragma unroll
        for (int kk = 0; kk < 64; kk += 16) {
            uint32_t aH[2][4], aL[2][4];
            #pragma unroll
            for (int mt = 0; mt < 2; mt++) {
                uint32_t off = (uint32_t)((wm * 32 + mt * 16 + a_r) * PITCH + kk + a_k) * 2;
                ldsm_x4(aH[mt], uA0 + off);
                ldsm_x4(aL[mt], uA1 + off);
            }
            uint32_t bH[4][4], bL[4][4];
            #pragma unroll
            for (int t = 0; t < 4; t++) {
                uint32_t off = (uint32_t)(kk + (lane & 15)) * PITCHB_BYTES
                             + (uint32_t)(wn * 64 + t * 16 + ((lane >> 4) << 3)) * 2;
                ldsm_x4_t(bH[t], uB0 + off);
                ldsm_x4_t(bL[t], uB1 + off);
            }
            #pragma unroll
            for (int mt = 0; mt < 2; mt++)
                #pragma unroll
                for (int t = 0; t < 4; t++)
                    #pragma unroll
                    for (int hf = 0; hf < 2; hf++) {
                        float* d = acc[mt][2 * t + hf];
                        mma16816(d, aH[mt], &bH[t][hf * 2]);
                        mma16816(d, aH[mt], &bL[t][hf * 2]);
                        mma16816(d, aL[mt], &bH[t][hf * 2]);
                    }
        }
        __syncthreads();
    }

    #pragma unroll
    for (int mt = 0; mt < 2; mt++) {
        const int r0 = wm * 32 + mt * 16 + (lane >> 2);
        #pragma unroll
        for (int nt = 0; nt < 8; nt++) {
            const int hl = wn * 64 + nt * 8 + (lane & 3) * 2;
            int c = c0 + r0;
            if (c < C)
                *(float2*)(out + ((size_t)b * C + c) * H + h0 + hl) =
                    make_float2(acc[mt][nt][0], acc[mt][nt][1]);
            if (c + 8 < C)
                *(float2*)(out + ((size_t)b * C + c + 8) * H + h0 + hl) =
                    make_float2(acc[mt][nt][2], acc[mt][nt][3]);
        }
    }
}

// ===========================================================================
// Launch
// ===========================================================================
extern "C" void kernel_launch(void* const* d_in, const int* in_sizes, int n_in,
                              void* d_out, int out_size)
{
    const float* x     = (const float*)d_in[0];
    const int*   masks = (const int*)d_in[1];
    const int*   cand  = (const int*)d_in[2];
    const float* w     = (const float*)d_in[3];

    const long long n0 = in_sizes[0];
    const long long n1 = in_sizes[1];
    const long long n2 = in_sizes[2];
    const long long n3 = in_sizes[3];

    const int H  = (int)(n0 / n1);
    const int HS = (int)((long long)out_size / n2);
    const int S  = HS - H;
    const int B  = (int)(n1 / S);
    const int C  = (int)(n2 / B);
    const int Lmax = (int)(n3 / H) - 1;

    float* logits = (float*)d_out;
    float* attn   = logits + (size_t)B * C * H;

    static bool attr_set = false;
    if (!attr_set) {
        cudaFuncSetAttribute(scores_mma_kernel, cudaFuncAttributeMaxDynamicSharedMemorySize, SMEM_SC);
        cudaFuncSetAttribute(logits_mma_kernel, cudaFuncAttributeMaxDynamicSharedMemorySize, SMEM_LG);
        attr_set = true;
    }

    dim3 blk(256);

    const int qtotal4 = B * C * H / 4;
    const int xtotal4 = B * S * H / 4;
    prep_q_kernel<<<(qtotal4 + 255) / 256, blk>>>(cand, w, H, Lmax, qtotal4, H / 4);
    prep_x_kernel<<<(xtotal4 + 255) / 256, blk>>>(x, xtotal4);

    dim3 g1(S / 128, (C + 127) / 128, B);
    scores_mma_kernel<<<g1, blk, SMEM_SC>>>(masks, attn, B, S, H, C);

    dim3 g2((unsigned)((size_t)B * C / 8));
    softmax_fused_kernel<<<g2, blk>>>(attn, S);

    dim3 g3(H / 128, (C + 127) / 128, B);
    logits_mma_kernel<<<g3, blk, SMEM_LG>>>(logits, B, S, H, C);
}

// round 9
// speedup vs baseline: 1.9337x; 1.0013x over previous
#include <cuda_runtime.h>
#include <cuda_bf16.h>
#include <math.h>
#include <stdint.h>

// Problem shape (validated across passing rounds)
#define CB 16
#define CS 1024
#define CH 256
#define CC 2000

__device__ __nv_bfloat16 g_qhi[CB * CC * CH];
__device__ __nv_bfloat16 g_qlo[CB * CC * CH];
__device__ __nv_bfloat16 g_xhi[CB * CS * CH];
__device__ __nv_bfloat16 g_xlo[CB * CS * CH];
__device__ __nv_bfloat16 g_ahi[CB * CC * CS];
__device__ __nv_bfloat16 g_alo[CB * CC * CS];

#define PITCH 72            // k-major tile row: 64 bf16 + 8 pad (144B)
#define TILE_B (128 * PITCH * 2)       // 18432 B
#define PITCHB_BYTES 272    // [k][n] tile row: 128 bf16 + 8 pad
#define TILEB_B (64 * PITCHB_BYTES)    // 17408 B

#define STAGE_SC (4 * TILE_B)                 // 73728 per stage (A0,A1,B0,B1)
#define SMEM_SC  (1024 + 3 * STAGE_SC)        // 222208
#define STAGE_LG (2 * TILE_B + 2 * TILEB_B)   // 71680 per stage
#define SMEM_LG  (3 * STAGE_LG)               // 215040

__device__ __forceinline__ uint32_t smem_u32(const void* p) {
    uint32_t a;
    asm("{ .reg .u64 t; cvta.to.shared.u64 t, %1; cvt.u32.u64 %0, t; }" : "=r"(a) : "l"(p));
    return a;
}
__device__ __forceinline__ void cp16(uint32_t dst, const void* src) {
    asm volatile("cp.async.cg.shared.global [%0], [%1], 16;" :: "r"(dst), "l"(src) : "memory");
}
__device__ __forceinline__ void cp_commit() { asm volatile("cp.async.commit_group;" ::: "memory"); }
__device__ __forceinline__ void cp_wait2()  { asm volatile("cp.async.wait_group 2;" ::: "memory"); }
__device__ __forceinline__ void cp_wait1()  { asm volatile("cp.async.wait_group 1;" ::: "memory"); }
__device__ __forceinline__ void cp_wait0()  { asm volatile("cp.async.wait_group 0;" ::: "memory"); }

__device__ __forceinline__ void ldsm_x4(uint32_t* r, uint32_t a) {
    asm volatile("ldmatrix.sync.aligned.m8n8.x4.shared.b16 {%0,%1,%2,%3}, [%4];"
                 : "=r"(r[0]), "=r"(r[1]), "=r"(r[2]), "=r"(r[3]) : "r"(a));
}
__device__ __forceinline__ void ldsm_x4_t(uint32_t* r, uint32_t a) {
    asm volatile("ldmatrix.sync.aligned.m8n8.x4.trans.shared.b16 {%0,%1,%2,%3}, [%4];"
                 : "=r"(r[0]), "=r"(r[1]), "=r"(r[2]), "=r"(r[3]) : "r"(a));
}
__device__ __forceinline__ void mma16816(float* d, const uint32_t* a, const uint32_t* b) {
    asm volatile(
        "mma.sync.aligned.m16n8k16.row.col.f32.bf16.bf16.f32 "
        "{%0,%1,%2,%3}, {%4,%5,%6,%7}, {%8,%9}, {%0,%1,%2,%3};"
        : "+f"(d[0]), "+f"(d[1]), "+f"(d[2]), "+f"(d[3])
        : "r"(a[0]), "r"(a[1]), "r"(a[2]), "r"(a[3]), "r"(b[0]), "r"(b[1]));
}
__device__ __forceinline__ void split2u(float a, float b, uint32_t& h, uint32_t& l) {
    __nv_bfloat162 hh, ll;
    hh.x = __float2bfloat16(a); hh.y = __float2bfloat16(b);
    ll.x = __float2bfloat16(a - __bfloat162float(hh.x));
    ll.y = __float2bfloat16(b - __bfloat162float(hh.y));
    h = *(uint32_t*)&hh; l = *(uint32_t*)&ll;
}

// ===========================================================================
// prep kernels: one-time fp32 -> bf16 hi/lo splits
// ===========================================================================
__global__ __launch_bounds__(256) void prep_q_kernel(
    const int* __restrict__ cand, const float* __restrict__ w,
    int H, int Lmax, int total4, int hd4)
{
    int i = blockIdx.x * 256 + threadIdx.x;
    if (i >= total4) return;
    int row  = i / hd4;
    int col4 = i - row * hd4;
    int lbl = cand[row];
    lbl = lbl < 0 ? 0 : (lbl > Lmax ? Lmax : lbl);
    float4 v = *(const float4*)(w + (size_t)lbl * H + col4 * 4);
    uint32_t h0, l0, h1, l1;
    split2u(v.x, v.y, h0, l0);
    split2u(v.z, v.w, h1, l1);
    *(uint2*)(g_qhi + (size_t)i * 4) = make_uint2(h0, h1);
    *(uint2*)(g_qlo + (size_t)i * 4) = make_uint2(l0, l1);
}

__global__ __launch_bounds__(256) void prep_x_kernel(const float* __restrict__ x, int total4)
{
    int i = blockIdx.x * 256 + threadIdx.x;
    if (i >= total4) return;
    float4 v = *(const float4*)(x + (size_t)i * 4);
    uint32_t h0, l0, h1, l1;
    split2u(v.x, v.y, h0, l0);
    split2u(v.z, v.w, h1, l1);
    *(uint2*)(g_xhi + (size_t)i * 4) = make_uint2(h0, h1);
    *(uint2*)(g_xlo + (size_t)i * 4) = make_uint2(l0, l1);
}

// ===========================================================================
// Kernel 1: scores = q . x^T  (masked -> -inf), 3-stage cp.async + HMMA
// ===========================================================================
__global__ __launch_bounds__(256) void scores_mma_kernel(
    const int* __restrict__ masks, float* __restrict__ attn,
    int B, int S, int H, int C)
{
    extern __shared__ char dsm[];
    const uint32_t sb = smem_u32(dsm);
    int* smask = (int*)dsm;

    const int tid = threadIdx.x;
    const int lane = tid & 31;
    const int wid = tid >> 5;
    const int wm = wid & 3;
    const int wn = wid >> 2;
    const int b  = blockIdx.z;
    const int c0 = blockIdx.y * 128;
    const int s0 = blockIdx.x * 128;

    if (tid < 128) smask[tid] = masks[(size_t)b * S + s0 + tid];

    const int a_r = lane & 15;
    const int a_k = (lane >> 4) * 8;
    const int b_n = (lane & 7) | (((lane >> 4) & 1) << 3);
    const int b_k = ((lane >> 3) & 1) * 8;

    float acc[2][8][4];
    #pragma unroll
    for (int i = 0; i < 2; i++)
        #pragma unroll
        for (int j = 0; j < 8; j++)
            #pragma unroll
            for (int q = 0; q < 4; q++) acc[i][j][q] = 0.f;

    auto prefetch = [&](int ch, int stg) {
        const int kc = ch << 6;
        const uint32_t A0 = sb + 1024 + stg * STAGE_SC;
        const uint32_t A1 = A0 + TILE_B;
        const uint32_t B0 = A0 + 2 * TILE_B;
        const uint32_t B1 = A0 + 3 * TILE_B;
        #pragma unroll
        for (int j = 0; j < 4; j++) {
            const int q = (tid << 2) + j;
            const int row = q >> 3;
            const int c16 = q & 7;
            const uint32_t soff = row * 144 + c16 * 16;
            int crow = c0 + row; if (crow >= C) crow = C - 1;
            const size_t qo = ((size_t)b * C + crow) * H + kc + c16 * 8;
            cp16(A0 + soff, g_qhi + qo);
            cp16(A1 + soff, g_qlo + qo);
            const size_t xo = ((size_t)b * S + s0 + row) * H + kc + c16 * 8;
            cp16(B0 + soff, g_xhi + xo);
            cp16(B1 + soff, g_xlo + xo);
        }
        cp_commit();
    };

    const int nch = H >> 6;      // 4
    prefetch(0, 0);
    if (nch > 1) prefetch(1, 1);

    int stg = 0;
    for (int ch = 0; ch < nch; ch++) {
        if (ch + 2 < nch) { prefetch(ch + 2, (stg + 2) % 3); cp_wait2(); }
        else if (ch + 1 < nch) cp_wait1();
        else cp_wait0();
        __syncthreads();

        const uint32_t uA0 = sb + 1024 + stg * STAGE_SC;
        const uint32_t uA1 = uA0 + TILE_B;
        const uint32_t uB0 = uA0 + 2 * TILE_B;
        const uint32_t uB1 = uA0 + 3 * TILE_B;

        #pragma unroll
        for (int kk = 0; kk < 64; kk += 16) {
            uint32_t aH[2][4], aL[2][4];
            #pragma unroll
            for (int mt = 0; mt < 2; mt++) {
                uint32_t off = (uint32_t)((wm * 32 + mt * 16 + a_r) * PITCH + kk + a_k) * 2;
                ldsm_x4(aH[mt], uA0 + off);
                ldsm_x4(aL[mt], uA1 + off);
            }
            uint32_t bH[4][4], bL[4][4];
            #pragma unroll
            for (int t = 0; t < 4; t++) {
                uint32_t off = (uint32_t)((wn * 64 + t * 16 + b_n) * PITCH + kk + b_k) * 2;
                ldsm_x4(bH[t], uB0 + off);
                ldsm_x4(bL[t], uB1 + off);
            }
            #pragma unroll
            for (int mt = 0; mt < 2; mt++)
                #pragma unroll
                for (int t = 0; t < 4; t++)
                    #pragma unroll
                    for (int hf = 0; hf < 2; hf++) {
                        float* d = acc[mt][2 * t + hf];
                        mma16816(d, aH[mt], &bH[t][hf * 2]);
                        mma16816(d, aH[mt], &bL[t][hf * 2]);
                        mma16816(d, aL[mt], &bH[t][hf * 2]);
                    }
        }
        __syncthreads();
        stg = (stg + 1) % 3;
    }

    #pragma unroll
    for (int mt = 0; mt < 2; mt++) {
        const int r0 = wm * 32 + mt * 16 + (lane >> 2);
        #pragma unroll
        for (int nt = 0; nt < 8; nt++) {
            const int sl = wn * 64 + nt * 8 + (lane & 3) * 2;
            const float ninf = -INFINITY;
            float2 o0, o1;
            o0.x = smask[sl]     ? acc[mt][nt][0] : ninf;
            o0.y = smask[sl + 1] ? acc[mt][nt][1] : ninf;
            o1.x = smask[sl]     ? acc[mt][nt][2] : ninf;
            o1.y = smask[sl + 1] ? acc[mt][nt][3] : ninf;
            int c = c0 + r0;
            if (c < C)
                *(float2*)(attn + ((size_t)b * C + c) * S + s0 + sl) = o0;
            if (c + 8 < C)
                *(float2*)(attn + ((size_t)b * C + c + 8) * S + s0 + sl) = o1;
        }
    }
}

// ===========================================================================
// Kernel 2: fused softmax — warp per row, single read, write fp32 + bf16 hi/lo
// ===========================================================================
__global__ __launch_bounds__(256) void softmax_fused_kernel(
    float* __restrict__ attn, int S)
{
    const int lane = threadIdx.x & 31;
    const int wrp  = threadIdx.x >> 5;
    const size_t row = (size_t)blockIdx.x * 8 + wrp;
    float* p = attn + row * (size_t)S;
    const int nf = S >> 7;

    float4 v[8];
    float m = -INFINITY;
    #pragma unroll
    for (int f = 0; f < 8; f++) {
        if (f < nf) {
            v[f] = ((const float4*)p)[lane + (f << 5)];
            m = fmaxf(m, fmaxf(fmaxf(v[f].x, v[f].y), fmaxf(v[f].z, v[f].w)));
        }
    }
    #pragma unroll
    for (int o = 16; o > 0; o >>= 1) m = fmaxf(m, __shfl_xor_sync(0xffffffffu, m, o));

    float s = 0.f;
    #pragma unroll
    for (int f = 0; f < 8; f++) {
        if (f < nf) {
            v[f].x = __expf(v[f].x - m); v[f].y = __expf(v[f].y - m);
            v[f].z = __expf(v[f].z - m); v[f].w = __expf(v[f].w - m);
            s += (v[f].x + v[f].y) + (v[f].z + v[f].w);
        }
    }
    #pragma unroll
    for (int o = 16; o > 0; o >>= 1) s += __shfl_xor_sync(0xffffffffu, s, o);
    const float inv = 1.0f / s;

    __nv_bfloat16* ph = g_ahi + row * (size_t)S;
    __nv_bfloat16* pl = g_alo + row * (size_t)S;
    #pragma unroll
    for (int f = 0; f < 8; f++) {
        if (f < nf) {
            float4 o;
            o.x = v[f].x * inv; o.y = v[f].y * inv;
            o.z = v[f].z * inv; o.w = v[f].w * inv;
            const int idx = lane + (f << 5);
            ((float4*)p)[idx] = o;
            uint32_t h0, l0, h1, l1;
            split2u(o.x, o.y, h0, l0);
            split2u(o.z, o.w, h1, l1);
            ((uint2*)ph)[idx] = make_uint2(h0, h1);
            ((uint2*)pl)[idx] = make_uint2(l0, l1);
        }
    }
}

// ===========================================================================
// Kernel 3: logits = attn . x — 3-stage cp.async both operands + HMMA
// ===========================================================================
__global__ __launch_bounds__(256) void logits_mma_kernel(
    float* __restrict__ out, int B, int S, int H, int C)
{
    extern __shared__ char dsm[];
    const uint32_t sb = smem_u32(dsm);

    const int tid = threadIdx.x;
    const int lane = tid & 31;
    const int wid = tid >> 5;
    const int wm = wid & 3;
    const int wn = wid >> 2;
    const int b  = blockIdx.z;
    const int c0 = blockIdx.y * 128;
    const int h0 = blockIdx.x * 128;

    const int a_r = lane & 15;
    const int a_k = (lane >> 4) * 8;

    float acc[2][8][4];
    #pragma unroll
    for (int i = 0; i < 2; i++)
        #pragma unroll
        for (int j = 0; j < 8; j++)
            #pragma unroll
            for (int q = 0; q < 4; q++) acc[i][j][q] = 0.f;

    auto prefetch = [&](int ch, int stg) {
        const int kc = ch << 6;
        const uint32_t A0 = sb + stg * STAGE_LG;
        const uint32_t A1 = A0 + TILE_B;
        const uint32_t B0 = A0 + 2 * TILE_B;
        const uint32_t B1 = B0 + TILEB_B;
        #pragma unroll
        for (int j = 0; j < 4; j++) {
            const int q = (tid << 2) + j;
            {   // A: attention hi/lo, [c][s] k-major
                const int row = q >> 3;
                const int c16 = q & 7;
                const uint32_t soff = row * 144 + c16 * 16;
                int crow = c0 + row; if (crow >= C) crow = C - 1;
                const size_t ao = ((size_t)b * C + crow) * S + kc + c16 * 8;
                cp16(A0 + soff, g_ahi + ao);
                cp16(A1 + soff, g_alo + ao);
            }
            {   // B: x hi/lo, [s][h] natural (trans ldsm later)
                const int row = q >> 4;
                const int c16 = q & 15;
                const uint32_t soff = row * PITCHB_BYTES + c16 * 16;
                const size_t xo = ((size_t)b * S + kc + row) * H + h0 + c16 * 8;
                cp16(B0 + soff, g_xhi + xo);
                cp16(B1 + soff, g_xlo + xo);
            }
        }
        cp_commit();
    };

    const int nch = S >> 6;      // 16
    prefetch(0, 0);
    prefetch(1, 1);

    int stg = 0;
    for (int ch = 0; ch < nch; ch++) {
        if (ch + 2 < nch) { prefetch(ch + 2, (stg + 2) % 3); cp_wait2(); }
        else if (ch + 1 < nch) cp_wait1();
        else cp_wait0();
        __syncthreads();

        const uint32_t uA0 = sb + stg * STAGE_LG;
        const uint32_t uA1 = uA0 + TILE_B;
        const uint32_t uB0 = uA0 + 2 * TILE_B;
        const uint32_t uB1 = uB0 + TILEB_B;

        #pragma unroll
        for (int kk = 0; kk < 64; kk += 16) {
            uint32_t aH[2][4], aL[2][4];
            #pragma unroll
            for (int mt = 0; mt < 2; mt++) {
                uint32_t off = (uint32_t)((wm * 32 + mt * 16 + a_r) * PITCH + kk + a_k) * 2;
                ldsm_x4(aH[mt], uA0 + off);
                ldsm_x4(aL[mt], uA1 + off);
            }
            uint32_t bH[4][4], bL[4][4];
            #pragma unroll
            for (int t = 0; t < 4; t++) {
                uint32_t off = (uint32_t)(kk + (lane & 15)) * PITCHB_BYTES
                             + (uint32_t)(wn * 64 + t * 16 + ((lane >> 4) << 3)) * 2;
                ldsm_x4_t(bH[t], uB0 + off);
                ldsm_x4_t(bL[t], uB1 + off);
            }
            #pragma unroll
            for (int mt = 0; mt < 2; mt++)
                #pragma unroll
                for (int t = 0; t < 4; t++)
                    #pragma unroll
                    for (int hf = 0; hf < 2; hf++) {
                        float* d = acc[mt][2 * t + hf];
                        mma16816(d, aH[mt], &bH[t][hf * 2]);
                        mma16816(d, aH[mt], &bL[t][hf * 2]);
                        mma16816(d, aL[mt], &bH[t][hf * 2]);
                    }
        }
        __syncthreads();
        stg = (stg + 1) % 3;
    }

    #pragma unroll
    for (int mt = 0; mt < 2; mt++) {
        const int r0 = wm * 32 + mt * 16 + (lane >> 2);
        #pragma unroll
        for (int nt = 0; nt < 8; nt++) {
            const int hl = wn * 64 + nt * 8 + (lane & 3) * 2;
            int c = c0 + r0;
            if (c < C)
                *(float2*)(out + ((size_t)b * C + c) * H + h0 + hl) =
                    make_float2(acc[mt][nt][0], acc[mt][nt][1]);
            if (c + 8 < C)
                *(float2*)(out + ((size_t)b * C + c + 8) * H + h0 + hl) =
                    make_float2(acc[mt][nt][2], acc[mt][nt][3]);
        }
    }
}

// ===========================================================================
// Launch
// ===========================================================================
extern "C" void kernel_launch(void* const* d_in, const int* in_sizes, int n_in,
                              void* d_out, int out_size)
{
    const float* x     = (const float*)d_in[0];
    const int*   masks = (const int*)d_in[1];
    const int*   cand  = (const int*)d_in[2];
    const float* w     = (const float*)d_in[3];

    const long long n0 = in_sizes[0];
    const long long n1 = in_sizes[1];
    const long long n2 = in_sizes[2];
    const long long n3 = in_sizes[3];

    const int H  = (int)(n0 / n1);
    const int HS = (int)((long long)out_size / n2);
    const int S  = HS - H;
    const int B  = (int)(n1 / S);
    const int C  = (int)(n2 / B);
    const int Lmax = (int)(n3 / H) - 1;

    float* logits = (float*)d_out;
    float* attn   = logits + (size_t)B * C * H;

    static bool attr_set = false;
    if (!attr_set) {
        cudaFuncSetAttribute(scores_mma_kernel, cudaFuncAttributeMaxDynamicSharedMemorySize, SMEM_SC);
        cudaFuncSetAttribute(logits_mma_kernel, cudaFuncAttributeMaxDynamicSharedMemorySize, SMEM_LG);
        attr_set = true;
    }

    dim3 blk(256);

    const int qtotal4 = B * C * H / 4;
    const int xtotal4 = B * S * H / 4;
    prep_q_kernel<<<(qtotal4 + 255) / 256, blk>>>(cand, w, H, Lmax, qtotal4, H / 4);
    prep_x_kernel<<<(xtotal4 + 255) / 256, blk>>>(x, xtotal4);

    dim3 g1(S / 128, (C + 127) / 128, B);
    scores_mma_kernel<<<g1, blk, SMEM_SC>>>(masks, attn, B, S, H, C);

    dim3 g2((unsigned)((size_t)B * C / 8));
    softmax_fused_kernel<<<g2, blk>>>(attn, S);

    dim3 g3(H / 128, (C + 127) / 128, B);
    logits_mma_kernel<<<g3, blk, SMEM_LG>>>(logits, B, S, H, C);
}

// round 10
// speedup vs baseline: 2.2401x; 1.1585x over previous
#include <cuda_runtime.h>
#include <cuda_bf16.h>
#include <math.h>
#include <stdint.h>

// Problem shape (validated across passing rounds)
#define CB 16
#define CS 1024
#define CH 256
#define CC 2000

__device__ __nv_bfloat16 g_qhi[CB * CC * CH];
__device__ __nv_bfloat16 g_qlo[CB * CC * CH];
__device__ __nv_bfloat16 g_xhi[CB * CS * CH];
__device__ __nv_bfloat16 g_xlo[CB * CS * CH];
__device__ __nv_bfloat16 g_ahi[CB * CC * CS];
__device__ __nv_bfloat16 g_alo[CB * CC * CS];

#define PITCH 72                 // k-major row: 64 bf16 + 8 pad (144 B)
#define TILE_A (256 * 144)       // 36864 B  (256 rows)
#define TILE_N (128 * 144)       // 18432 B  (128 rows)
#define PITCHB_BYTES 272         // [k][n] row: 128 bf16 + 8 pad
#define TILEB_LG (64 * PITCHB_BYTES)  // 17408 B

#define STAGE_SC (2 * TILE_A + 2 * TILE_N)     // 110592
#define SMEM_SC  (1024 + 2 * STAGE_SC)         // 222208
#define STAGE_LG (2 * TILE_A + 2 * TILEB_LG)   // 108544
#define SMEM_LG  (2 * STAGE_LG)                // 217088

__device__ __forceinline__ uint32_t smem_u32(const void* p) {
    uint32_t a;
    asm("{ .reg .u64 t; cvta.to.shared.u64 t, %1; cvt.u32.u64 %0, t; }" : "=r"(a) : "l"(p));
    return a;
}
__device__ __forceinline__ void cp16(uint32_t dst, const void* src) {
    asm volatile("cp.async.cg.shared.global [%0], [%1], 16;" :: "r"(dst), "l"(src) : "memory");
}
__device__ __forceinline__ void cp_commit() { asm volatile("cp.async.commit_group;" ::: "memory"); }
__device__ __forceinline__ void cp_wait1()  { asm volatile("cp.async.wait_group 1;" ::: "memory"); }
__device__ __forceinline__ void cp_wait0()  { asm volatile("cp.async.wait_group 0;" ::: "memory"); }

__device__ __forceinline__ void ldsm_x4(uint32_t* r, uint32_t a) {
    asm volatile("ldmatrix.sync.aligned.m8n8.x4.shared.b16 {%0,%1,%2,%3}, [%4];"
                 : "=r"(r[0]), "=r"(r[1]), "=r"(r[2]), "=r"(r[3]) : "r"(a));
}
__device__ __forceinline__ void ldsm_x4_t(uint32_t* r, uint32_t a) {
    asm volatile("ldmatrix.sync.aligned.m8n8.x4.trans.shared.b16 {%0,%1,%2,%3}, [%4];"
                 : "=r"(r[0]), "=r"(r[1]), "=r"(r[2]), "=r"(r[3]) : "r"(a));
}
__device__ __forceinline__ void mma16816(float* d, const uint32_t* a, const uint32_t* b) {
    asm volatile(
        "mma.sync.aligned.m16n8k16.row.col.f32.bf16.bf16.f32 "
        "{%0,%1,%2,%3}, {%4,%5,%6,%7}, {%8,%9}, {%0,%1,%2,%3};"
        : "+f"(d[0]), "+f"(d[1]), "+f"(d[2]), "+f"(d[3])
        : "r"(a[0]), "r"(a[1]), "r"(a[2]), "r"(a[3]), "r"(b[0]), "r"(b[1]));
}
__device__ __forceinline__ void split2u(float a, float b, uint32_t& h, uint32_t& l) {
    __nv_bfloat162 hh, ll;
    hh.x = __float2bfloat16(a); hh.y = __float2bfloat16(b);
    ll.x = __float2bfloat16(a - __bfloat162float(hh.x));
    ll.y = __float2bfloat16(b - __bfloat162float(hh.y));
    h = *(uint32_t*)&hh; l = *(uint32_t*)&ll;
}

// ===========================================================================
// prep kernels: one-time fp32 -> bf16 hi/lo splits
// ===========================================================================
__global__ __launch_bounds__(256) void prep_q_kernel(
    const int* __restrict__ cand, const float* __restrict__ w,
    int H, int Lmax, int total4, int hd4)
{
    int i = blockIdx.x * 256 + threadIdx.x;
    if (i >= total4) return;
    int row  = i / hd4;
    int col4 = i - row * hd4;
    int lbl = cand[row];
    lbl = lbl < 0 ? 0 : (lbl > Lmax ? Lmax : lbl);
    float4 v = *(const float4*)(w + (size_t)lbl * H + col4 * 4);
    uint32_t h0, l0, h1, l1;
    split2u(v.x, v.y, h0, l0);
    split2u(v.z, v.w, h1, l1);
    *(uint2*)(g_qhi + (size_t)i * 4) = make_uint2(h0, h1);
    *(uint2*)(g_qlo + (size_t)i * 4) = make_uint2(l0, l1);
}

__global__ __launch_bounds__(256) void prep_x_kernel(const float* __restrict__ x, int total4)
{
    int i = blockIdx.x * 256 + threadIdx.x;
    if (i >= total4) return;
    float4 v = *(const float4*)(x + (size_t)i * 4);
    uint32_t h0, l0, h1, l1;
    split2u(v.x, v.y, h0, l0);
    split2u(v.z, v.w, h1, l1);
    *(uint2*)(g_xhi + (size_t)i * 4) = make_uint2(h0, h1);
    *(uint2*)(g_xlo + (size_t)i * 4) = make_uint2(l0, l1);
}

// ===========================================================================
// Kernel 1: scores = q . x^T  (masked -> -inf)
// 512 threads, tile 256c x 128s, K chunk 64, 2-stage cp.async + HMMA
// ===========================================================================
__global__ __launch_bounds__(512, 1) void scores_mma_kernel(
    const int* __restrict__ masks, float* __restrict__ attn,
    int B, int S, int H, int C)
{
    extern __shared__ char dsm[];
    const uint32_t sb = smem_u32(dsm);
    int* smask = (int*)dsm;

    const int tid = threadIdx.x;
    const int lane = tid & 31;
    const int wid = tid >> 5;
    const int wm = wid & 7;        // 8 m-groups of 32 c
    const int wn = wid >> 3;       // 2 n-groups of 64 s
    const int b  = blockIdx.z;
    const int c0 = blockIdx.y * 256;
    const int s0 = blockIdx.x * 128;

    if (tid < 128) smask[tid] = masks[(size_t)b * S + s0 + tid];

    const int a_r = lane & 15;
    const int a_k = (lane >> 4) * 8;
    const int b_n = (lane & 7) | (((lane >> 4) & 1) << 3);
    const int b_k = ((lane >> 3) & 1) * 8;

    float acc[2][8][4];
    #pragma unroll
    for (int i = 0; i < 2; i++)
        #pragma unroll
        for (int j = 0; j < 8; j++)
            #pragma unroll
            for (int q = 0; q < 4; q++) acc[i][j][q] = 0.f;

    auto prefetch = [&](int ch, int stg) {
        const int kc = ch << 6;
        const uint32_t A0 = sb + 1024 + stg * STAGE_SC;
        const uint32_t A1 = A0 + TILE_A;
        const uint32_t B0 = A1 + TILE_A;
        const uint32_t B1 = B0 + TILE_N;
        #pragma unroll
        for (int j = 0; j < 4; j++) {          // A: 256 rows x 128B
            const int q = (tid << 2) + j;      // 0..2047
            const int row = q >> 3;
            const int c16 = q & 7;
            const uint32_t soff = row * 144 + c16 * 16;
            int crow = c0 + row; if (crow >= C) crow = C - 1;
            const size_t qo = ((size_t)b * C + crow) * H + kc + c16 * 8;
            cp16(A0 + soff, g_qhi + qo);
            cp16(A1 + soff, g_qlo + qo);
        }
        #pragma unroll
        for (int j = 0; j < 2; j++) {          // B: 128 rows x 128B
            const int q = (tid << 1) + j;      // 0..1023
            const int row = q >> 3;
            const int c16 = q & 7;
            const uint32_t soff = row * 144 + c16 * 16;
            const size_t xo = ((size_t)b * S + s0 + row) * H + kc + c16 * 8;
            cp16(B0 + soff, g_xhi + xo);
            cp16(B1 + soff, g_xlo + xo);
        }
        cp_commit();
    };

    const int nch = H >> 6;      // 4
    prefetch(0, 0);
    for (int ch = 0; ch < nch; ch++) {
        if (ch + 1 < nch) { prefetch(ch + 1, (ch + 1) & 1); cp_wait1(); }
        else cp_wait0();
        __syncthreads();

        const uint32_t uA0 = sb + 1024 + (ch & 1) * STAGE_SC;
        const uint32_t uA1 = uA0 + TILE_A;
        const uint32_t uB0 = uA1 + TILE_A;
        const uint32_t uB1 = uB0 + TILE_N;

        #pragma unroll
        for (int kk = 0; kk < 64; kk += 16) {
            uint32_t aH[2][4], aL[2][4];
            #pragma unroll
            for (int mt = 0; mt < 2; mt++) {
                uint32_t off = (uint32_t)((wm * 32 + mt * 16 + a_r) * PITCH + kk + a_k) * 2;
                ldsm_x4(aH[mt], uA0 + off);
                ldsm_x4(aL[mt], uA1 + off);
            }
            uint32_t bH[4][4], bL[4][4];
            #pragma unroll
            for (int t = 0; t < 4; t++) {
                uint32_t off = (uint32_t)((wn * 64 + t * 16 + b_n) * PITCH + kk + b_k) * 2;
                ldsm_x4(bH[t], uB0 + off);
                ldsm_x4(bL[t], uB1 + off);
            }
            #pragma unroll
            for (int mt = 0; mt < 2; mt++)
                #pragma unroll
                for (int t = 0; t < 4; t++)
                    #pragma unroll
                    for (int hf = 0; hf < 2; hf++) {
                        float* d = acc[mt][2 * t + hf];
                        mma16816(d, aH[mt], &bH[t][hf * 2]);
                        mma16816(d, aH[mt], &bL[t][hf * 2]);
                        mma16816(d, aL[mt], &bH[t][hf * 2]);
                    }
        }
        __syncthreads();
    }

    #pragma unroll
    for (int mt = 0; mt < 2; mt++) {
        const int r0 = wm * 32 + mt * 16 + (lane >> 2);
        #pragma unroll
        for (int nt = 0; nt < 8; nt++) {
            const int sl = wn * 64 + nt * 8 + (lane & 3) * 2;
            const float ninf = -INFINITY;
            float2 o0, o1;
            o0.x = smask[sl]     ? acc[mt][nt][0] : ninf;
            o0.y = smask[sl + 1] ? acc[mt][nt][1] : ninf;
            o1.x = smask[sl]     ? acc[mt][nt][2] : ninf;
            o1.y = smask[sl + 1] ? acc[mt][nt][3] : ninf;
            int c = c0 + r0;
            if (c < C)
                *(float2*)(attn + ((size_t)b * C + c) * S + s0 + sl) = o0;
            if (c + 8 < C)
                *(float2*)(attn + ((size_t)b * C + c + 8) * S + s0 + sl) = o1;
        }
    }
}

// ===========================================================================
// Kernel 2: fused softmax — warp per row, single read, write fp32 + bf16 hi/lo
// ===========================================================================
__global__ __launch_bounds__(256) void softmax_fused_kernel(
    float* __restrict__ attn, int S)
{
    const int lane = threadIdx.x & 31;
    const int wrp  = threadIdx.x >> 5;
    const size_t row = (size_t)blockIdx.x * 8 + wrp;
    float* p = attn + row * (size_t)S;
    const int nf = S >> 7;

    float4 v[8];
    float m = -INFINITY;
    #pragma unroll
    for (int f = 0; f < 8; f++) {
        if (f < nf) {
            v[f] = ((const float4*)p)[lane + (f << 5)];
            m = fmaxf(m, fmaxf(fmaxf(v[f].x, v[f].y), fmaxf(v[f].z, v[f].w)));
        }
    }
    #pragma unroll
    for (int o = 16; o > 0; o >>= 1) m = fmaxf(m, __shfl_xor_sync(0xffffffffu, m, o));

    float s = 0.f;
    #pragma unroll
    for (int f = 0; f < 8; f++) {
        if (f < nf) {
            v[f].x = __expf(v[f].x - m); v[f].y = __expf(v[f].y - m);
            v[f].z = __expf(v[f].z - m); v[f].w = __expf(v[f].w - m);
            s += (v[f].x + v[f].y) + (v[f].z + v[f].w);
        }
    }
    #pragma unroll
    for (int o = 16; o > 0; o >>= 1) s += __shfl_xor_sync(0xffffffffu, s, o);
    const float inv = 1.0f / s;

    __nv_bfloat16* ph = g_ahi + row * (size_t)S;
    __nv_bfloat16* pl = g_alo + row * (size_t)S;
    #pragma unroll
    for (int f = 0; f < 8; f++) {
        if (f < nf) {
            float4 o;
            o.x = v[f].x * inv; o.y = v[f].y * inv;
            o.z = v[f].z * inv; o.w = v[f].w * inv;
            const int idx = lane + (f << 5);
            ((float4*)p)[idx] = o;
            uint32_t h0, l0, h1, l1;
            split2u(o.x, o.y, h0, l0);
            split2u(o.z, o.w, h1, l1);
            ((uint2*)ph)[idx] = make_uint2(h0, h1);
            ((uint2*)pl)[idx] = make_uint2(l0, l1);
        }
    }
}

// ===========================================================================
// Kernel 3: logits = attn . x
// 512 threads, tile 256c x 128h, K chunk 64, 2-stage cp.async + HMMA
// ===========================================================================
__global__ __launch_bounds__(512, 1) void logits_mma_kernel(
    float* __restrict__ out, int B, int S, int H, int C)
{
    extern __shared__ char dsm[];
    const uint32_t sb = smem_u32(dsm);

    const int tid = threadIdx.x;
    const int lane = tid & 31;
    const int wid = tid >> 5;
    const int wm = wid & 7;
    const int wn = wid >> 3;
    const int b  = blockIdx.z;
    const int c0 = blockIdx.y * 256;
    const int h0 = blockIdx.x * 128;

    const int a_r = lane & 15;
    const int a_k = (lane >> 4) * 8;

    float acc[2][8][4];
    #pragma unroll
    for (int i = 0; i < 2; i++)
        #pragma unroll
        for (int j = 0; j < 8; j++)
            #pragma unroll
            for (int q = 0; q < 4; q++) acc[i][j][q] = 0.f;

    auto prefetch = [&](int ch, int stg) {
        const int kc = ch << 6;
        const uint32_t A0 = sb + stg * STAGE_LG;
        const uint32_t A1 = A0 + TILE_A;
        const uint32_t B0 = A1 + TILE_A;
        const uint32_t B1 = B0 + TILEB_LG;
        #pragma unroll
        for (int j = 0; j < 4; j++) {          // A: attention hi/lo [c][s], 256 rows
            const int q = (tid << 2) + j;
            const int row = q >> 3;
            const int c16 = q & 7;
            const uint32_t soff = row * 144 + c16 * 16;
            int crow = c0 + row; if (crow >= C) crow = C - 1;
            const size_t ao = ((size_t)b * C + crow) * S + kc + c16 * 8;
            cp16(A0 + soff, g_ahi + ao);
            cp16(A1 + soff, g_alo + ao);
        }
        #pragma unroll
        for (int j = 0; j < 2; j++) {          // B: x hi/lo [s][h], 64 rows x 256B
            const int q = (tid << 1) + j;      // 0..1023
            const int row = q >> 4;
            const int c16 = q & 15;
            const uint32_t soff = row * PITCHB_BYTES + c16 * 16;
            const size_t xo = ((size_t)b * S + kc + row) * H + h0 + c16 * 8;
            cp16(B0 + soff, g_xhi + xo);
            cp16(B1 + soff, g_xlo + xo);
        }
        cp_commit();
    };

    const int nch = S >> 6;      // 16
    prefetch(0, 0);
    for (int ch = 0; ch < nch; ch++) {
        if (ch + 1 < nch) { prefetch(ch + 1, (ch + 1) & 1); cp_wait1(); }
        else cp_wait0();
        __syncthreads();

        const uint32_t uA0 = sb + (ch & 1) * STAGE_LG;
        const uint32_t uA1 = uA0 + TILE_A;
        const uint32_t uB0 = uA1 + TILE_A;
        const uint32_t uB1 = uB0 + TILEB_LG;

        #pragma unroll
        for (int kk = 0; kk < 64; kk += 16) {
            uint32_t aH[2][4], aL[2][4];
            #pragma unroll
            for (int mt = 0; mt < 2; mt++) {
                uint32_t off = (uint32_t)((wm * 32 + mt * 16 + a_r) * PITCH + kk + a_k) * 2;
                ldsm_x4(aH[mt], uA0 + off);
                ldsm_x4(aL[mt], uA1 + off);
            }
            uint32_t bH[4][4], bL[4][4];
            #pragma unroll
            for (int t = 0; t < 4; t++) {
                uint32_t off = (uint32_t)(kk + (lane & 15)) * PITCHB_BYTES
                             + (uint32_t)(wn * 64 + t * 16 + ((lane >> 4) << 3)) * 2;
                ldsm_x4_t(bH[t], uB0 + off);
                ldsm_x4_t(bL[t], uB1 + off);
            }
            #pragma unroll
            for (int mt = 0; mt < 2; mt++)
                #pragma unroll
                for (int t = 0; t < 4; t++)
                    #pragma unroll
                    for (int hf = 0; hf < 2; hf++) {
                        float* d = acc[mt][2 * t + hf];
                        mma16816(d, aH[mt], &bH[t][hf * 2]);
                        mma16816(d, aH[mt], &bL[t][hf * 2]);
                        mma16816(d, aL[mt], &bH[t][hf * 2]);
                    }
        }
        __syncthreads();
    }

    #pragma unroll
    for (int mt = 0; mt < 2; mt++) {
        const int r0 = wm * 32 + mt * 16 + (lane >> 2);
        #pragma unroll
        for (int nt = 0; nt < 8; nt++) {
            const int hl = wn * 64 + nt * 8 + (lane & 3) * 2;
            int c = c0 + r0;
            if (c < C)
                *(float2*)(out + ((size_t)b * C + c) * H + h0 + hl) =
                    make_float2(acc[mt][nt][0], acc[mt][nt][1]);
            if (c + 8 < C)
                *(float2*)(out + ((size_t)b * C + c + 8) * H + h0 + hl) =
                    make_float2(acc[mt][nt][2], acc[mt][nt][3]);
        }
    }
}

// ===========================================================================
// Launch
// ===========================================================================
extern "C" void kernel_launch(void* const* d_in, const int* in_sizes, int n_in,
                              void* d_out, int out_size)
{
    const float* x     = (const float*)d_in[0];
    const int*   masks = (const int*)d_in[1];
    const int*   cand  = (const int*)d_in[2];
    const float* w     = (const float*)d_in[3];

    const long long n0 = in_sizes[0];
    const long long n1 = in_sizes[1];
    const long long n2 = in_sizes[2];
    const long long n3 = in_sizes[3];

    const int H  = (int)(n0 / n1);
    const int HS = (int)((long long)out_size / n2);
    const int S  = HS - H;
    const int B  = (int)(n1 / S);
    const int C  = (int)(n2 / B);
    const int Lmax = (int)(n3 / H) - 1;

    float* logits = (float*)d_out;
    float* attn   = logits + (size_t)B * C * H;

    static bool attr_set = false;
    if (!attr_set) {
        cudaFuncSetAttribute(scores_mma_kernel, cudaFuncAttributeMaxDynamicSharedMemorySize, SMEM_SC);
        cudaFuncSetAttribute(logits_mma_kernel, cudaFuncAttributeMaxDynamicSharedMemorySize, SMEM_LG);
        attr_set = true;
    }

    const int qtotal4 = B * C * H / 4;
    const int xtotal4 = B * S * H / 4;
    prep_q_kernel<<<(qtotal4 + 255) / 256, 256>>>(cand, w, H, Lmax, qtotal4, H / 4);
    prep_x_kernel<<<(xtotal4 + 255) / 256, 256>>>(x, xtotal4);

    dim3 g1(S / 128, (C + 255) / 256, B);
    scores_mma_kernel<<<g1, 512, SMEM_SC>>>(masks, attn, B, S, H, C);

    dim3 g2((unsigned)((size_t)B * C / 8));
    softmax_fused_kernel<<<g2, 256>>>(attn, S);

    dim3 g3(H / 128, (C + 255) / 256, B);
    logits_mma_kernel<<<g3, 512, SMEM_LG>>>(logits, B, S, H, C);
}